// round 1
// baseline (speedup 1.0000x reference)
#include <cuda_runtime.h>
#include <math.h>
#include <stdint.h>

#define Nn 100000
#define Ee 800000
// feature dims
#define FIN 128
#define H1  256
#define OUTD 128

// ---------------- scratch (static device globals; no runtime allocation) ----------------
__device__ float g_Xt[(size_t)Nn * H1];    // relu(x@fc0_w+b)      [N,256]
__device__ float g_Xagg[(size_t)Nn * H1];  // M @ Xt               [N,256]
__device__ float g_deg[Nn];
__device__ float g_dinv[Nn];
__device__ int   g_count[Nn];
__device__ int   g_rowptr[Nn];
__device__ int   g_cursor[Nn];
__device__ int   g_csr_src[Ee];
__device__ float g_csr_coef[Ee];           // dinv[src]*w
__device__ float g_Wc[H1 * 256];           // combined weights, cols interleaved: 2j=z, 2j+1=h
__device__ float g_bc[256];                // combined bias, interleaved
__device__ int   g_bsums[128];             // scan partials

// ---------------- graph prep ----------------
__global__ void k_init() {
    int i = blockIdx.x * blockDim.x + threadIdx.x;
    if (i < Nn) { g_deg[i] = 1.0f; g_count[i] = 0; g_cursor[i] = 0; }
}

__global__ void k_edge_accum(const int* __restrict__ dst, const float* __restrict__ ew) {
    int e = blockIdx.x * blockDim.x + threadIdx.x;
    if (e < Ee) {
        int d = dst[e];
        atomicAdd(&g_deg[d], ew[e]);
        atomicAdd(&g_count[d], 1);
    }
}

__global__ void k_dinv() {
    int i = blockIdx.x * blockDim.x + threadIdx.x;
    if (i < Nn) g_dinv[i] = rsqrtf(g_deg[i]);   // deg >= 1 always (self loop)
}

// exclusive scan of g_count into g_rowptr (3 kernels)
__global__ void k_scan_block() {
    __shared__ int s[1024];
    int i = blockIdx.x * 1024 + threadIdx.x;
    int v = (i < Nn) ? g_count[i] : 0;
    s[threadIdx.x] = v;
    __syncthreads();
    #pragma unroll
    for (int off = 1; off < 1024; off <<= 1) {
        int t = (threadIdx.x >= off) ? s[threadIdx.x - off] : 0;
        __syncthreads();
        s[threadIdx.x] += t;
        __syncthreads();
    }
    if (i < Nn) g_rowptr[i] = s[threadIdx.x] - v;       // exclusive
    if (threadIdx.x == 1023) g_bsums[blockIdx.x] = s[1023];
}

__global__ void k_scan_sums(int nb) {
    if (threadIdx.x == 0 && blockIdx.x == 0) {
        int acc = 0;
        for (int b = 0; b < nb; b++) { int t = g_bsums[b]; g_bsums[b] = acc; acc += t; }
    }
}

__global__ void k_scan_add() {
    int i = blockIdx.x * 1024 + threadIdx.x;
    if (i < Nn) g_rowptr[i] += g_bsums[blockIdx.x];
}

__global__ void k_fill(const int* __restrict__ src, const int* __restrict__ dst,
                       const float* __restrict__ ew) {
    int e = blockIdx.x * blockDim.x + threadIdx.x;
    if (e < Ee) {
        int d = dst[e], s = src[e];
        int pos = g_rowptr[d] + atomicAdd(&g_cursor[d], 1);
        g_csr_src[pos]  = s;
        g_csr_coef[pos] = g_dinv[s] * ew[e];
    }
}

// ---------------- fold conv weights through lin weights ----------------
// Wc[k][2j]   = sum_t conv_z_w[k][t] * lin_z_w[t][j]
// Wc[k][2j+1] = sum_t conv_h_w[k][t] * lin_h_w[t][j]
__global__ void k_build_wc(const float* __restrict__ czw, const float* __restrict__ chw,
                           const float* __restrict__ lzw, const float* __restrict__ lhw) {
    __shared__ float rz[128], rh[128];
    int k = blockIdx.x;        // 0..255
    int j = threadIdx.x;       // 0..127
    rz[j] = czw[k * 128 + j];
    rh[j] = chw[k * 128 + j];
    __syncthreads();
    float az = 0.f, ah = 0.f;
    #pragma unroll 4
    for (int t = 0; t < 128; t++) {
        az += rz[t] * lzw[t * 128 + j];
        ah += rh[t] * lhw[t * 128 + j];
    }
    g_Wc[k * 256 + 2 * j]     = az;
    g_Wc[k * 256 + 2 * j + 1] = ah;
}

__global__ void k_build_bc(const float* __restrict__ czb, const float* __restrict__ chb,
                           const float* __restrict__ lzw, const float* __restrict__ lhw,
                           const float* __restrict__ lzb, const float* __restrict__ lhb) {
    int j = threadIdx.x;       // 0..127
    float az = lzb[j], ah = lhb[j];
    #pragma unroll 4
    for (int t = 0; t < 128; t++) {
        az += czb[t] * lzw[t * 128 + j];
        ah += chb[t] * lhw[t * 128 + j];
    }
    g_bc[2 * j]     = az;
    g_bc[2 * j + 1] = ah;
}

// ---------------- GEMM: C = epi(A[M,K] @ B[K,256] + bias) ----------------
// EPI 0: relu, C = g_Xt row stride 256 (A = x input param)
// EPI 1: GRU combine on interleaved cols, write h to C (row stride 128);
//        A = g_Xagg, B = g_Wc, bias = g_bc
template<int K, int EPI>
__global__ __launch_bounds__(256) void k_gemm(const float* __restrict__ Ain,
                                              const float* __restrict__ Bin,
                                              const float* __restrict__ biasin,
                                              float* __restrict__ Cout, int M) {
    const float* A    = (EPI == 0) ? Ain    : g_Xagg;
    const float* B    = (EPI == 0) ? Bin    : g_Wc;
    const float* bias = (EPI == 0) ? biasin : g_bc;
    float* C          = (EPI == 0) ? g_Xt   : Cout;

    __shared__ float As[128][17];                 // [row][k], padded
    __shared__ __align__(16) float Bs[16 * 128];  // [k][col]

    int tid = threadIdx.x;
    int tx = tid & 15, ty = tid >> 4;
    int row0 = blockIdx.y * 128;
    int col0 = blockIdx.x * 128;

    float acc[8][8];
    #pragma unroll
    for (int i = 0; i < 8; i++)
        #pragma unroll
        for (int j = 0; j < 8; j++) acc[i][j] = 0.f;

    for (int kb = 0; kb < K; kb += 16) {
        // load A tile (128x16), zero-pad past M
        #pragma unroll
        for (int l = 0; l < 2; l++) {
            int idx = tid + l * 256;          // float4 index 0..511
            int r = idx >> 2;
            int kc = (idx & 3) * 4;
            float4 v = make_float4(0.f, 0.f, 0.f, 0.f);
            int gr = row0 + r;
            if (gr < M) v = *(const float4*)(A + (size_t)gr * K + kb + kc);
            As[r][kc + 0] = v.x; As[r][kc + 1] = v.y;
            As[r][kc + 2] = v.z; As[r][kc + 3] = v.w;
        }
        // load B tile (16x128)
        #pragma unroll
        for (int l = 0; l < 2; l++) {
            int idx = tid + l * 256;          // float4 index 0..511
            int k = idx >> 5;
            int c4 = idx & 31;
            float4 v = *(const float4*)(B + (size_t)(kb + k) * 256 + col0 + c4 * 4);
            *(float4*)(Bs + k * 128 + c4 * 4) = v;
        }
        __syncthreads();
        #pragma unroll
        for (int k = 0; k < 16; k++) {
            float a[8], b[8];
            #pragma unroll
            for (int i = 0; i < 8; i++) a[i] = As[ty * 8 + i][k];
            float4 b0 = *(float4*)(Bs + k * 128 + tx * 8);
            float4 b1 = *(float4*)(Bs + k * 128 + tx * 8 + 4);
            b[0] = b0.x; b[1] = b0.y; b[2] = b0.z; b[3] = b0.w;
            b[4] = b1.x; b[5] = b1.y; b[6] = b1.z; b[7] = b1.w;
            #pragma unroll
            for (int i = 0; i < 8; i++)
                #pragma unroll
                for (int j = 0; j < 8; j++)
                    acc[i][j] += a[i] * b[j];
        }
        __syncthreads();
    }

    #pragma unroll
    for (int i = 0; i < 8; i++) {
        int r = row0 + ty * 8 + i;
        if (r >= M) break;
        if (EPI == 0) {
            float o[8];
            #pragma unroll
            for (int j = 0; j < 8; j++) {
                int c = col0 + tx * 8 + j;
                o[j] = fmaxf(acc[i][j] + bias[c], 0.f);
            }
            float4* p = (float4*)(C + (size_t)r * 256 + col0 + tx * 8);
            p[0] = make_float4(o[0], o[1], o[2], o[3]);
            p[1] = make_float4(o[4], o[5], o[6], o[7]);
        } else {
            float hv[4];
            #pragma unroll
            for (int p = 0; p < 4; p++) {
                int cz = col0 + tx * 8 + 2 * p;
                float gz = acc[i][2 * p]     + bias[cz];
                float gh = acc[i][2 * p + 1] + bias[cz + 1];
                float z = 1.f / (1.f + expf(-gz));
                hv[p] = (1.f - z) * tanhf(gh);
            }
            *(float4*)(C + (size_t)r * 128 + (col0 >> 1) + tx * 4) =
                make_float4(hv[0], hv[1], hv[2], hv[3]);
        }
    }
}

// ---------------- sparse aggregation: Xagg = D^-1/2 (A+I) D^-1/2 Xt ----------------
__global__ __launch_bounds__(256) void k_aggregate() {
    int d = blockIdx.x;
    int f = threadIdx.x;                  // 0..255
    float di = g_dinv[d];
    float acc = di * g_Xt[(size_t)d * 256 + f];   // self loop coef = dinv[d]
    int beg = g_rowptr[d];
    int end = beg + g_count[d];
    for (int e = beg; e < end; e++) {
        int s = g_csr_src[e];
        float c = g_csr_coef[e];
        acc += c * g_Xt[(size_t)s * 256 + f];
    }
    g_Xagg[(size_t)d * 256 + f] = acc * di;
}

// ---------------- out[i] = relu(h[i]) . fc_w + fc_b ----------------
__global__ void k_out(const float* __restrict__ h, const float* __restrict__ fcw,
                      const float* __restrict__ fcb, float* __restrict__ out) {
    int gwarp = (blockIdx.x * blockDim.x + threadIdx.x) >> 5;
    int lane = threadIdx.x & 31;
    if (gwarp >= Nn) return;
    const float* hr = h + (size_t)gwarp * 128;
    float s = 0.f;
    #pragma unroll
    for (int f = lane; f < 128; f += 32) s += fmaxf(hr[f], 0.f) * fcw[f];
    #pragma unroll
    for (int o = 16; o; o >>= 1) s += __shfl_xor_sync(0xffffffffu, s, o);
    if (lane == 0) out[gwarp] = s + fcb[0];
}

// ---------------- launch ----------------
extern "C" void kernel_launch(void* const* d_in, const int* in_sizes, int n_in,
                              void* d_out, int out_size) {
    const float* x     = (const float*)d_in[0];
    const int*   ei    = (const int*)d_in[1];
    const float* ew    = (const float*)d_in[2];
    const float* fc0_w = (const float*)d_in[3];
    const float* fc0_b = (const float*)d_in[4];
    // d_in[5] = att: softmax over a single element == 1.0, drops out
    const float* czw   = (const float*)d_in[6];
    const float* czb   = (const float*)d_in[7];
    const float* lzw   = (const float*)d_in[8];
    const float* lzb   = (const float*)d_in[9];
    // d_in[10..13] = conv_r / lin_r: dead code since H0 == 0 (R only enters via H*R)
    const float* chw   = (const float*)d_in[14];
    const float* chb   = (const float*)d_in[15];
    const float* lhw   = (const float*)d_in[16];
    const float* lhb   = (const float*)d_in[17];
    const float* fcw   = (const float*)d_in[18];
    const float* fcb   = (const float*)d_in[19];

    const int* src = ei;
    const int* dst = ei + Ee;

    float* out  = (float*)d_out;       // [N]
    float* hout = out + Nn;            // [N,128]

    const int nb = (Nn + 1023) / 1024; // 98

    // graph prep
    k_init<<<(Nn + 255) / 256, 256>>>();
    k_edge_accum<<<(Ee + 255) / 256, 256>>>(dst, ew);
    k_dinv<<<(Nn + 255) / 256, 256>>>();
    k_scan_block<<<nb, 1024>>>();
    k_scan_sums<<<1, 32>>>(nb);
    k_scan_add<<<nb, 1024>>>();
    k_fill<<<(Ee + 255) / 256, 256>>>(src, dst, ew);

    // weight folding
    k_build_wc<<<256, 128>>>(czw, chw, lzw, lhw);
    k_build_bc<<<1, 128>>>(czb, chb, lzw, lhw, lzb, lhb);

    // Xt = relu(x @ fc0_w + fc0_b)
    dim3 g1(2, (Nn + 127) / 128);
    k_gemm<128, 0><<<g1, 256>>>(x, fc0_w, fc0_b, nullptr, Nn);

    // Xagg = M @ Xt
    k_aggregate<<<Nn, 256>>>();

    // h = (1 - sigmoid(Xagg@Wz + bz)) * tanh(Xagg@Wh + bh), written into d_out
    dim3 g2(2, (Nn + 127) / 128);
    k_gemm<256, 1><<<g2, 256>>>(nullptr, nullptr, nullptr, hout, Nn);

    // out = relu(h) @ fc_w + fc_b
    k_out<<<(Nn * 32 + 255) / 256, 256>>>(hout, fcw, fcb, out);
}

// round 2
// speedup vs baseline: 1.7508x; 1.7508x over previous
#include <cuda_runtime.h>
#include <math.h>
#include <stdint.h>

#define Nn 100000
#define Ee 800000
#define FIN 128
#define H1  256
#define OUTD 128

// ---------------- scratch (static device globals; no runtime allocation) ----------------
__device__ float g_Xt[(size_t)Nn * H1];    // relu(x@fc0_w+b)      [N,256]
__device__ float g_Xagg[(size_t)Nn * H1];  // M @ Xt               [N,256]
__device__ float g_deg[Nn];
__device__ float g_dinv[Nn];
__device__ int   g_count[Nn];
__device__ int   g_rowptr[Nn];
__device__ int   g_cursor[Nn];
__device__ int   g_csr_src[Ee];
__device__ float g_csr_coef[Ee];           // dinv[src]*w
__device__ float g_Wc[H1 * 256];           // combined weights, cols interleaved: 2j=z, 2j+1=h
__device__ float g_bc[256];                // combined bias, interleaved
__device__ int   g_bsums[128];             // scan partials

// ---------------- graph prep ----------------
__global__ void k_init() {
    int i = blockIdx.x * blockDim.x + threadIdx.x;
    if (i < Nn) { g_deg[i] = 1.0f; g_count[i] = 0; g_cursor[i] = 0; }
}

__global__ void k_edge_accum(const int* __restrict__ dst, const float* __restrict__ ew) {
    int e = blockIdx.x * blockDim.x + threadIdx.x;
    if (e < Ee) {
        int d = dst[e];
        atomicAdd(&g_deg[d], ew[e]);
        atomicAdd(&g_count[d], 1);
    }
}

__global__ void k_dinv() {
    int i = blockIdx.x * blockDim.x + threadIdx.x;
    if (i < Nn) g_dinv[i] = rsqrtf(g_deg[i]);
}

__global__ void k_scan_block() {
    __shared__ int s[1024];
    int i = blockIdx.x * 1024 + threadIdx.x;
    int v = (i < Nn) ? g_count[i] : 0;
    s[threadIdx.x] = v;
    __syncthreads();
    #pragma unroll
    for (int off = 1; off < 1024; off <<= 1) {
        int t = (threadIdx.x >= off) ? s[threadIdx.x - off] : 0;
        __syncthreads();
        s[threadIdx.x] += t;
        __syncthreads();
    }
    if (i < Nn) g_rowptr[i] = s[threadIdx.x] - v;
    if (threadIdx.x == 1023) g_bsums[blockIdx.x] = s[1023];
}

__global__ void k_scan_sums(int nb) {
    if (threadIdx.x == 0 && blockIdx.x == 0) {
        int acc = 0;
        for (int b = 0; b < nb; b++) { int t = g_bsums[b]; g_bsums[b] = acc; acc += t; }
    }
}

__global__ void k_scan_add() {
    int i = blockIdx.x * 1024 + threadIdx.x;
    if (i < Nn) g_rowptr[i] += g_bsums[blockIdx.x];
}

__global__ void k_fill(const int* __restrict__ src, const int* __restrict__ dst,
                       const float* __restrict__ ew) {
    int e = blockIdx.x * blockDim.x + threadIdx.x;
    if (e < Ee) {
        int d = dst[e], s = src[e];
        int pos = g_rowptr[d] + atomicAdd(&g_cursor[d], 1);
        g_csr_src[pos]  = s;
        g_csr_coef[pos] = g_dinv[s] * ew[e];
    }
}

// ---------------- fold conv weights through lin weights ----------------
__global__ void k_build_wc(const float* __restrict__ czw, const float* __restrict__ chw,
                           const float* __restrict__ lzw, const float* __restrict__ lhw) {
    __shared__ float rz[128], rh[128];
    int k = blockIdx.x;
    int j = threadIdx.x;
    rz[j] = czw[k * 128 + j];
    rh[j] = chw[k * 128 + j];
    __syncthreads();
    float az = 0.f, ah = 0.f;
    #pragma unroll 4
    for (int t = 0; t < 128; t++) {
        az += rz[t] * lzw[t * 128 + j];
        ah += rh[t] * lhw[t * 128 + j];
    }
    g_Wc[k * 256 + 2 * j]     = az;
    g_Wc[k * 256 + 2 * j + 1] = ah;
}

__global__ void k_build_bc(const float* __restrict__ czb, const float* __restrict__ chb,
                           const float* __restrict__ lzw, const float* __restrict__ lhw,
                           const float* __restrict__ lzb, const float* __restrict__ lhb) {
    int j = threadIdx.x;
    float az = lzb[j], ah = lhb[j];
    #pragma unroll 4
    for (int t = 0; t < 128; t++) {
        az += czb[t] * lzw[t * 128 + j];
        ah += chb[t] * lhw[t * 128 + j];
    }
    g_bc[2 * j]     = az;
    g_bc[2 * j + 1] = ah;
}

// ---------------- tf32 helpers ----------------
__device__ __forceinline__ float to_tf32(float x) {
    float r;
    asm("cvt.rna.tf32.f32 %0, %1;" : "=f"(r) : "f"(x));
    return r;
}

__device__ __forceinline__ void mma_tf32(float* c, const uint32_t* a, const uint32_t* b) {
    asm volatile(
        "mma.sync.aligned.m16n8k8.row.col.f32.tf32.tf32.f32 "
        "{%0,%1,%2,%3},{%4,%5,%6,%7},{%8,%9},{%0,%1,%2,%3};\n"
        : "+f"(c[0]), "+f"(c[1]), "+f"(c[2]), "+f"(c[3])
        : "r"(a[0]), "r"(a[1]), "r"(a[2]), "r"(a[3]), "r"(b[0]), "r"(b[1]));
}

// ---------------- tensor-core GEMM: C = epi(A[M,K] @ B[K,256] + bias) ----------------
// BM=128, BN=128, BK=32, 8 warps (4 in m, 2 in n), warp tile 32x64,
// per warp: 2 m16 tiles x 8 n8 tiles of m16n8k8 tf32 mma.
// EPI 0: relu -> g_Xt (row stride 256)
// EPI 1: GRU on interleaved (z,h) column pairs -> Cout (row stride 128)
#define AS_LD 36
#define BS_LD 136
template<int K, int EPI>
__global__ __launch_bounds__(256) void k_gemm_tc(const float* __restrict__ Ain,
                                                 const float* __restrict__ Bin,
                                                 const float* __restrict__ biasin,
                                                 float* __restrict__ Cout, int M) {
    const float* A    = (EPI == 0) ? Ain    : g_Xagg;
    const float* B    = (EPI == 0) ? Bin    : g_Wc;
    const float* bias = (EPI == 0) ? biasin : g_bc;
    float* C          = (EPI == 0) ? g_Xt   : Cout;

    __shared__ float As[128 * AS_LD];   // [m][k], bank = (4m + k) % 32 -> conflict-free frags
    __shared__ float Bs[32 * BS_LD];    // [k][n], bank = (8k + n) % 32 -> conflict-free frags

    const int tid  = threadIdx.x;
    const int lane = tid & 31;
    const int w    = tid >> 5;
    const int wy   = w & 3;             // m-warp 0..3
    const int wx   = w >> 2;            // n-warp 0..1
    const int g    = lane >> 2;         // groupID 0..7
    const int cq   = lane & 3;          // tid-in-group 0..3

    const int row0 = blockIdx.y * 128;
    const int col0 = blockIdx.x * 128;
    const int woffm = wy * 32;
    const int woffn = wx * 64;

    float acc[2][8][4];
    #pragma unroll
    for (int mt = 0; mt < 2; mt++)
        #pragma unroll
        for (int nt = 0; nt < 8; nt++)
            #pragma unroll
            for (int i = 0; i < 4; i++) acc[mt][nt][i] = 0.f;

    for (int kb = 0; kb < K; kb += 32) {
        // A tile: 128x32, guarded + zero-padded past M
        #pragma unroll
        for (int l = 0; l < 4; l++) {
            int idx = tid + l * 256;          // float4 idx 0..1023
            int r  = idx >> 3;
            int kc = (idx & 7) << 2;
            float4 v = make_float4(0.f, 0.f, 0.f, 0.f);
            if (row0 + r < M) v = *(const float4*)(A + (size_t)(row0 + r) * K + kb + kc);
            v.x = to_tf32(v.x); v.y = to_tf32(v.y);
            v.z = to_tf32(v.z); v.w = to_tf32(v.w);
            *(float4*)(As + r * AS_LD + kc) = v;
        }
        // B tile: 32x128
        #pragma unroll
        for (int l = 0; l < 4; l++) {
            int idx = tid + l * 256;
            int k  = idx >> 5;
            int nc = (idx & 31) << 2;
            float4 v = *(const float4*)(B + (size_t)(kb + k) * 256 + col0 + nc);
            v.x = to_tf32(v.x); v.y = to_tf32(v.y);
            v.z = to_tf32(v.z); v.w = to_tf32(v.w);
            *(float4*)(Bs + k * BS_LD + nc) = v;
        }
        __syncthreads();

        #pragma unroll
        for (int kk = 0; kk < 32; kk += 8) {
            uint32_t af[2][4], bf[8][2];
            #pragma unroll
            for (int mt = 0; mt < 2; mt++) {
                int mb = woffm + mt * 16;
                af[mt][0] = __float_as_uint(As[(mb + g)     * AS_LD + kk + cq]);
                af[mt][1] = __float_as_uint(As[(mb + g + 8) * AS_LD + kk + cq]);
                af[mt][2] = __float_as_uint(As[(mb + g)     * AS_LD + kk + cq + 4]);
                af[mt][3] = __float_as_uint(As[(mb + g + 8) * AS_LD + kk + cq + 4]);
            }
            #pragma unroll
            for (int nt = 0; nt < 8; nt++) {
                int n = woffn + nt * 8 + g;
                bf[nt][0] = __float_as_uint(Bs[(kk + cq)     * BS_LD + n]);
                bf[nt][1] = __float_as_uint(Bs[(kk + cq + 4) * BS_LD + n]);
            }
            #pragma unroll
            for (int mt = 0; mt < 2; mt++)
                #pragma unroll
                for (int nt = 0; nt < 8; nt++)
                    mma_tf32(acc[mt][nt], af[mt], bf[nt]);
        }
        __syncthreads();
    }

    // epilogue — C frag: c0:(row g,   col 2cq), c1:(g, 2cq+1), c2:(g+8, 2cq), c3:(g+8, 2cq+1)
    #pragma unroll
    for (int mt = 0; mt < 2; mt++) {
        int r0 = row0 + woffm + mt * 16 + g;
        int r1 = r0 + 8;
        #pragma unroll
        for (int nt = 0; nt < 8; nt++) {
            int col = col0 + woffn + nt * 8 + 2 * cq;  // even column
            float b0 = bias[col], b1 = bias[col + 1];
            if (EPI == 0) {
                if (r0 < M) {
                    float2 o = make_float2(fmaxf(acc[mt][nt][0] + b0, 0.f),
                                           fmaxf(acc[mt][nt][1] + b1, 0.f));
                    *(float2*)(C + (size_t)r0 * 256 + col) = o;
                }
                if (r1 < M) {
                    float2 o = make_float2(fmaxf(acc[mt][nt][2] + b0, 0.f),
                                           fmaxf(acc[mt][nt][3] + b1, 0.f));
                    *(float2*)(C + (size_t)r1 * 256 + col) = o;
                }
            } else {
                int oc = col >> 1;   // (z,h) pair index -> h column
                if (r0 < M) {
                    float z = 1.f / (1.f + expf(-(acc[mt][nt][0] + b0)));
                    C[(size_t)r0 * 128 + oc] = (1.f - z) * tanhf(acc[mt][nt][1] + b1);
                }
                if (r1 < M) {
                    float z = 1.f / (1.f + expf(-(acc[mt][nt][2] + b0)));
                    C[(size_t)r1 * 128 + oc] = (1.f - z) * tanhf(acc[mt][nt][3] + b1);
                }
            }
        }
    }
}

// ---------------- sparse aggregation: Xagg = D^-1/2 (A+I) D^-1/2 Xt ----------------
__global__ __launch_bounds__(256) void k_aggregate() {
    int d = blockIdx.x;
    int f = threadIdx.x;
    float di = g_dinv[d];
    float acc = di * g_Xt[(size_t)d * 256 + f];
    int beg = g_rowptr[d];
    int end = beg + g_count[d];
    for (int e = beg; e < end; e++) {
        int s = g_csr_src[e];
        float c = g_csr_coef[e];
        acc += c * g_Xt[(size_t)s * 256 + f];
    }
    g_Xagg[(size_t)d * 256 + f] = acc * di;
}

// ---------------- out[i] = relu(h[i]) . fc_w + fc_b ----------------
__global__ void k_out(const float* __restrict__ h, const float* __restrict__ fcw,
                      const float* __restrict__ fcb, float* __restrict__ out) {
    int gwarp = (blockIdx.x * blockDim.x + threadIdx.x) >> 5;
    int lane = threadIdx.x & 31;
    if (gwarp >= Nn) return;
    const float* hr = h + (size_t)gwarp * 128;
    float s = 0.f;
    #pragma unroll
    for (int f = lane; f < 128; f += 32) s += fmaxf(hr[f], 0.f) * fcw[f];
    #pragma unroll
    for (int o = 16; o; o >>= 1) s += __shfl_xor_sync(0xffffffffu, s, o);
    if (lane == 0) out[gwarp] = s + fcb[0];
}

// ---------------- launch ----------------
extern "C" void kernel_launch(void* const* d_in, const int* in_sizes, int n_in,
                              void* d_out, int out_size) {
    const float* x     = (const float*)d_in[0];
    const int*   ei    = (const int*)d_in[1];
    const float* ew    = (const float*)d_in[2];
    const float* fc0_w = (const float*)d_in[3];
    const float* fc0_b = (const float*)d_in[4];
    // d_in[5] = att: softmax over one element == 1.0
    const float* czw   = (const float*)d_in[6];
    const float* czb   = (const float*)d_in[7];
    const float* lzw   = (const float*)d_in[8];
    const float* lzb   = (const float*)d_in[9];
    // d_in[10..13] dead (H0 == 0 kills the R branch)
    const float* chw   = (const float*)d_in[14];
    const float* chb   = (const float*)d_in[15];
    const float* lhw   = (const float*)d_in[16];
    const float* lhb   = (const float*)d_in[17];
    const float* fcw   = (const float*)d_in[18];
    const float* fcb   = (const float*)d_in[19];

    const int* src = ei;
    const int* dst = ei + Ee;

    float* out  = (float*)d_out;
    float* hout = out + Nn;

    const int nb = (Nn + 1023) / 1024;

    k_init<<<(Nn + 255) / 256, 256>>>();
    k_edge_accum<<<(Ee + 255) / 256, 256>>>(dst, ew);
    k_dinv<<<(Nn + 255) / 256, 256>>>();
    k_scan_block<<<nb, 1024>>>();
    k_scan_sums<<<1, 32>>>(nb);
    k_scan_add<<<nb, 1024>>>();
    k_fill<<<(Ee + 255) / 256, 256>>>(src, dst, ew);

    k_build_wc<<<256, 128>>>(czw, chw, lzw, lhw);
    k_build_bc<<<1, 128>>>(czb, chb, lzw, lhw, lzb, lhb);

    dim3 g1(2, (Nn + 127) / 128);
    k_gemm_tc<128, 0><<<g1, 256>>>(x, fc0_w, fc0_b, nullptr, Nn);

    k_aggregate<<<Nn, 256>>>();

    dim3 g2(2, (Nn + 127) / 128);
    k_gemm_tc<256, 1><<<g2, 256>>>(nullptr, nullptr, nullptr, hout, Nn);

    k_out<<<(Nn * 32 + 255) / 256, 256>>>(hout, fcw, fcb, out);
}

// round 3
// speedup vs baseline: 1.8270x; 1.0435x over previous
#include <cuda_runtime.h>
#include <math.h>
#include <stdint.h>

#define Nn 100000
#define Ee 800000
#define FIN 128
#define H1  256
#define OUTD 128

// ---------------- scratch (static device globals) ----------------
__device__ float g_Xt[(size_t)Nn * H1];    // rna(relu(x@fc0_w+b))   [N,256] (tf32-rounded)
__device__ float g_G[(size_t)Nn * H1];     // Xt @ Wc                [N,256] (fp32 gates, pre-agg)
__device__ float g_deg[Nn];
__device__ float g_dinv[Nn];
__device__ int   g_count[Nn];
__device__ int   g_rowptr[Nn];
__device__ int   g_cursor[Nn];
__device__ int   g_csr_src[Ee];
__device__ float g_csr_coef[Ee];           // dinv[src]*w
__device__ float g_Wc[H1 * 256];           // combined weights (tf32-rounded), cols interleaved
__device__ float g_bc[256];                // combined bias, interleaved (z,h)
__device__ float g_Wb0[FIN * H1];          // tf32-rounded fc0_w
__device__ int   g_bsums[128];

// ---------------- helpers ----------------
__device__ __forceinline__ float to_tf32(float x) {
    float r;
    asm("cvt.rna.tf32.f32 %0, %1;" : "=f"(r) : "f"(x));
    return r;
}

__device__ __forceinline__ void mma_tf32(float* c, const uint32_t* a, const uint32_t* b) {
    asm volatile(
        "mma.sync.aligned.m16n8k8.row.col.f32.tf32.tf32.f32 "
        "{%0,%1,%2,%3},{%4,%5,%6,%7},{%8,%9},{%0,%1,%2,%3};\n"
        : "+f"(c[0]), "+f"(c[1]), "+f"(c[2]), "+f"(c[3])
        : "r"(a[0]), "r"(a[1]), "r"(a[2]), "r"(a[3]), "r"(b[0]), "r"(b[1]));
}

__device__ __forceinline__ uint32_t smem_u32(const void* p) {
    uint32_t a;
    asm("{ .reg .u64 t; cvta.to.shared.u64 t, %1; cvt.u32.u64 %0, t; }" : "=r"(a) : "l"(p));
    return a;
}

__device__ __forceinline__ void cp_async16(uint32_t dst, const void* src, int szbytes) {
    asm volatile("cp.async.cg.shared.global [%0], [%1], 16, %2;\n"
                 :: "r"(dst), "l"(src), "r"(szbytes));
}
#define CP_COMMIT() asm volatile("cp.async.commit_group;\n" ::: "memory")
#define CP_WAIT1()  asm volatile("cp.async.wait_group 1;\n" ::: "memory")

// ---------------- graph prep ----------------
__global__ void k_init() {
    int i = blockIdx.x * blockDim.x + threadIdx.x;
    if (i < Nn) { g_deg[i] = 1.0f; g_count[i] = 0; g_cursor[i] = 0; }
}

__global__ void k_edge_accum(const int* __restrict__ dst, const float* __restrict__ ew) {
    int e = blockIdx.x * blockDim.x + threadIdx.x;
    if (e < Ee) {
        int d = dst[e];
        atomicAdd(&g_deg[d], ew[e]);
        atomicAdd(&g_count[d], 1);
    }
}

__global__ void k_dinv() {
    int i = blockIdx.x * blockDim.x + threadIdx.x;
    if (i < Nn) g_dinv[i] = rsqrtf(g_deg[i]);
}

__global__ void k_scan_block() {
    __shared__ int s[1024];
    int i = blockIdx.x * 1024 + threadIdx.x;
    int v = (i < Nn) ? g_count[i] : 0;
    s[threadIdx.x] = v;
    __syncthreads();
    #pragma unroll
    for (int off = 1; off < 1024; off <<= 1) {
        int t = (threadIdx.x >= off) ? s[threadIdx.x - off] : 0;
        __syncthreads();
        s[threadIdx.x] += t;
        __syncthreads();
    }
    if (i < Nn) g_rowptr[i] = s[threadIdx.x] - v;
    if (threadIdx.x == 1023) g_bsums[blockIdx.x] = s[1023];
}

__global__ void k_scan_sums(int nb) {
    if (threadIdx.x == 0 && blockIdx.x == 0) {
        int acc = 0;
        for (int b = 0; b < nb; b++) { int t = g_bsums[b]; g_bsums[b] = acc; acc += t; }
    }
}

__global__ void k_scan_add() {
    int i = blockIdx.x * 1024 + threadIdx.x;
    if (i < Nn) g_rowptr[i] += g_bsums[blockIdx.x];
}

__global__ void k_fill(const int* __restrict__ src, const int* __restrict__ dst,
                       const float* __restrict__ ew) {
    int e = blockIdx.x * blockDim.x + threadIdx.x;
    if (e < Ee) {
        int d = dst[e], s = src[e];
        int pos = g_rowptr[d] + atomicAdd(&g_cursor[d], 1);
        g_csr_src[pos]  = s;
        g_csr_coef[pos] = g_dinv[s] * ew[e];
    }
}

// ---------------- weight prep ----------------
__global__ void k_round_b0(const float* __restrict__ w) {
    int i = blockIdx.x * blockDim.x + threadIdx.x;
    if (i < FIN * H1) g_Wb0[i] = to_tf32(w[i]);
}

__global__ void k_build_wc(const float* __restrict__ czw, const float* __restrict__ chw,
                           const float* __restrict__ lzw, const float* __restrict__ lhw) {
    __shared__ float rz[128], rh[128];
    int k = blockIdx.x;
    int j = threadIdx.x;
    rz[j] = czw[k * 128 + j];
    rh[j] = chw[k * 128 + j];
    __syncthreads();
    float az = 0.f, ah = 0.f;
    #pragma unroll 4
    for (int t = 0; t < 128; t++) {
        az += rz[t] * lzw[t * 128 + j];
        ah += rh[t] * lhw[t * 128 + j];
    }
    g_Wc[k * 256 + 2 * j]     = to_tf32(az);
    g_Wc[k * 256 + 2 * j + 1] = to_tf32(ah);
}

__global__ void k_build_bc(const float* __restrict__ czb, const float* __restrict__ chb,
                           const float* __restrict__ lzw, const float* __restrict__ lhw,
                           const float* __restrict__ lzb, const float* __restrict__ lhb) {
    int j = threadIdx.x;
    float az = lzb[j], ah = lhb[j];
    #pragma unroll 4
    for (int t = 0; t < 128; t++) {
        az += czb[t] * lzw[t * 128 + j];
        ah += chb[t] * lhw[t * 128 + j];
    }
    g_bc[2 * j]     = az;
    g_bc[2 * j + 1] = ah;
}

// ---------------- pipelined tf32 tensor-core GEMM ----------------
// C = epi(A[M,K] @ B[K,256])
// EPI 0: relu+bias, tf32-round, -> g_Xt (stride 256). A = x (CVTA), B = g_Wb0.
// EPI 1: raw gates -> g_G (stride 256). A = g_Xt, B = g_Wc. No bias (added post-agg).
#define AS_LD 36
#define BS_LD 136
template<int K, int EPI, bool CVTA>
__global__ __launch_bounds__(256, 2) void k_gemm_tc(const float* __restrict__ Ain,
                                                    const float* __restrict__ biasin,
                                                    int M) {
    const float* A    = (EPI == 0) ? Ain   : g_Xt;
    const float* B    = (EPI == 0) ? g_Wb0 : g_Wc;
    float* C          = (EPI == 0) ? g_Xt  : g_G;

    __shared__ float As[2][128 * AS_LD];
    __shared__ float Bs[2][32 * BS_LD];

    const int tid  = threadIdx.x;
    const int lane = tid & 31;
    const int w    = tid >> 5;
    const int wy   = w & 3;
    const int wx   = w >> 2;
    const int g    = lane >> 2;
    const int cq   = lane & 3;

    const int row0 = blockIdx.y * 128;
    const int col0 = blockIdx.x * 128;
    const int woffm = wy * 32;
    const int woffn = wx * 64;

    uint32_t sA[2], sB[2];
    sA[0] = smem_u32(&As[0][0]); sA[1] = smem_u32(&As[1][0]);
    sB[0] = smem_u32(&Bs[0][0]); sB[1] = smem_u32(&Bs[1][0]);

    float acc[2][8][4];
    #pragma unroll
    for (int mt = 0; mt < 2; mt++)
        #pragma unroll
        for (int nt = 0; nt < 8; nt++)
            #pragma unroll
            for (int i = 0; i < 4; i++) acc[mt][nt][i] = 0.f;

    auto load_stage = [&](int st, int kb) {
        #pragma unroll
        for (int l = 0; l < 4; l++) {
            int idx = tid + l * 256;
            int r  = idx >> 3;
            int kc = (idx & 7) << 2;
            int gr = row0 + r;
            int ok = (gr < M);
            const float* gp = A + (size_t)(ok ? gr : (M - 1)) * K + kb + kc;
            cp_async16(sA[st] + (uint32_t)(r * AS_LD + kc) * 4u, gp, ok ? 16 : 0);
        }
        #pragma unroll
        for (int l = 0; l < 4; l++) {
            int idx = tid + l * 256;
            int k  = idx >> 5;
            int nc = (idx & 31) << 2;
            cp_async16(sB[st] + (uint32_t)(k * BS_LD + nc) * 4u,
                       B + (size_t)(kb + k) * 256 + col0 + nc, 16);
        }
    };

    const int NKB = K / 32;
    load_stage(0, 0);
    CP_COMMIT();

    for (int kbi = 0; kbi < NKB; kbi++) {
        if (kbi + 1 < NKB) load_stage((kbi + 1) & 1, (kbi + 1) * 32);
        CP_COMMIT();
        CP_WAIT1();
        __syncthreads();
        const float* as = As[kbi & 1];
        const float* bs = Bs[kbi & 1];

        #pragma unroll
        for (int kk = 0; kk < 32; kk += 8) {
            uint32_t af[2][4], bf[8][2];
            #pragma unroll
            for (int mt = 0; mt < 2; mt++) {
                int mb = woffm + mt * 16;
                float a0 = as[(mb + g)     * AS_LD + kk + cq];
                float a1 = as[(mb + g + 8) * AS_LD + kk + cq];
                float a2 = as[(mb + g)     * AS_LD + kk + cq + 4];
                float a3 = as[(mb + g + 8) * AS_LD + kk + cq + 4];
                if (CVTA) { a0 = to_tf32(a0); a1 = to_tf32(a1); a2 = to_tf32(a2); a3 = to_tf32(a3); }
                af[mt][0] = __float_as_uint(a0); af[mt][1] = __float_as_uint(a1);
                af[mt][2] = __float_as_uint(a2); af[mt][3] = __float_as_uint(a3);
            }
            #pragma unroll
            for (int nt = 0; nt < 8; nt++) {
                int n = woffn + nt * 8 + g;
                bf[nt][0] = __float_as_uint(bs[(kk + cq)     * BS_LD + n]);
                bf[nt][1] = __float_as_uint(bs[(kk + cq + 4) * BS_LD + n]);
            }
            #pragma unroll
            for (int mt = 0; mt < 2; mt++)
                #pragma unroll
                for (int nt = 0; nt < 8; nt++)
                    mma_tf32(acc[mt][nt], af[mt], bf[nt]);
        }
        __syncthreads();
    }

    // epilogue — frag c0:(g, 2cq), c1:(g, 2cq+1), c2:(g+8, 2cq), c3:(g+8, 2cq+1)
    #pragma unroll
    for (int mt = 0; mt < 2; mt++) {
        int r0 = row0 + woffm + mt * 16 + g;
        int r1 = r0 + 8;
        #pragma unroll
        for (int nt = 0; nt < 8; nt++) {
            int col = col0 + woffn + nt * 8 + 2 * cq;
            if (EPI == 0) {
                float b0 = biasin[col], b1 = biasin[col + 1];
                if (r0 < M) {
                    float2 o = make_float2(to_tf32(fmaxf(acc[mt][nt][0] + b0, 0.f)),
                                           to_tf32(fmaxf(acc[mt][nt][1] + b1, 0.f)));
                    *(float2*)(C + (size_t)r0 * 256 + col) = o;
                }
                if (r1 < M) {
                    float2 o = make_float2(to_tf32(fmaxf(acc[mt][nt][2] + b0, 0.f)),
                                           to_tf32(fmaxf(acc[mt][nt][3] + b1, 0.f)));
                    *(float2*)(C + (size_t)r1 * 256 + col) = o;
                }
            } else {
                if (r0 < M)
                    *(float2*)(C + (size_t)r0 * 256 + col) = make_float2(acc[mt][nt][0], acc[mt][nt][1]);
                if (r1 < M)
                    *(float2*)(C + (size_t)r1 * 256 + col) = make_float2(acc[mt][nt][2], acc[mt][nt][3]);
            }
        }
    }
}

// ---------------- fused aggregate + bias + GRU + output head ----------------
// gates[d] = dinv[d] * ( G[d] + sum_e coef[e]*G[src[e]] ) + bc
// h[d][j]  = (1 - sigmoid(gates[2j])) * tanh(gates[2j+1])
// out[d]   = relu(h[d]) . fc_w + fc_b
__global__ __launch_bounds__(256) void k_agg_gru(const float* __restrict__ fcw,
                                                 const float* __restrict__ fcb,
                                                 float* __restrict__ hout,
                                                 float* __restrict__ out) {
    __shared__ float s_red[8];
    int d = blockIdx.x;
    int f = threadIdx.x;
    float di = g_dinv[d];
    const float* Grow = g_G;

    float a0 = Grow[(size_t)d * 256 + f];   // self loop (coef folded via di*di below)
    float a1 = 0.f, a2 = 0.f, a3 = 0.f;

    int beg = g_rowptr[d];
    int cnt = g_count[d];
    int e = beg, end = beg + cnt;
    for (; e + 4 <= end; e += 4) {
        int   s0 = g_csr_src[e],     s1 = g_csr_src[e + 1];
        int   s2 = g_csr_src[e + 2], s3 = g_csr_src[e + 3];
        float c0 = g_csr_coef[e],     c1 = g_csr_coef[e + 1];
        float c2 = g_csr_coef[e + 2], c3 = g_csr_coef[e + 3];
        a0 += c0 * Grow[(size_t)s0 * 256 + f];
        a1 += c1 * Grow[(size_t)s1 * 256 + f];
        a2 += c2 * Grow[(size_t)s2 * 256 + f];
        a3 += c3 * Grow[(size_t)s3 * 256 + f];
    }
    for (; e < end; e++) {
        a0 += g_csr_coef[e] * Grow[(size_t)g_csr_src[e] * 256 + f];
    }
    float gate = ((a0 + a1) + (a2 + a3)) * di;
    // self loop: coef should be di (not 1): a0 included G[d] with implicit coef 1,
    // actual self coef = di, and we multiplied total by di, so self term = di*G[d]... 
    // need di*di*G[d]: fix by adding (di*di - di)*G[d] ... instead compute exactly:
    gate = gate + (di * di - di) * Grow[(size_t)d * 256 + f];
    gate += g_bc[f];

    float other = __shfl_xor_sync(0xffffffffu, gate, 1);
    float h = 0.f, prod = 0.f;
    if ((f & 1) == 0) {
        float z = 1.f / (1.f + expf(-gate));
        h = (1.f - z) * tanhf(other);
        hout[(size_t)d * 128 + (f >> 1)] = h;
        prod = fmaxf(h, 0.f) * fcw[f >> 1];
    }
    // block reduce prod
    #pragma unroll
    for (int o = 16; o; o >>= 1) prod += __shfl_xor_sync(0xffffffffu, prod, o);
    if ((f & 31) == 0) s_red[f >> 5] = prod;
    __syncthreads();
    if (f == 0) {
        float s = 0.f;
        #pragma unroll
        for (int i = 0; i < 8; i++) s += s_red[i];
        out[d] = s + fcb[0];
    }
}

// ---------------- launch ----------------
extern "C" void kernel_launch(void* const* d_in, const int* in_sizes, int n_in,
                              void* d_out, int out_size) {
    const float* x     = (const float*)d_in[0];
    const int*   ei    = (const int*)d_in[1];
    const float* ew    = (const float*)d_in[2];
    const float* fc0_w = (const float*)d_in[3];
    const float* fc0_b = (const float*)d_in[4];
    // d_in[5] = att: softmax over one element == 1.0
    const float* czw   = (const float*)d_in[6];
    const float* czb   = (const float*)d_in[7];
    const float* lzw   = (const float*)d_in[8];
    const float* lzb   = (const float*)d_in[9];
    // d_in[10..13] dead (H0 == 0 kills the R branch)
    const float* chw   = (const float*)d_in[14];
    const float* chb   = (const float*)d_in[15];
    const float* lhw   = (const float*)d_in[16];
    const float* lhb   = (const float*)d_in[17];
    const float* fcw   = (const float*)d_in[18];
    const float* fcb   = (const float*)d_in[19];

    const int* src = ei;
    const int* dst = ei + Ee;

    float* out  = (float*)d_out;
    float* hout = out + Nn;

    const int nb = (Nn + 1023) / 1024;

    // order chosen so GEMM1 is launch index 3 (ncu capture slot)
    k_init<<<(Nn + 255) / 256, 256>>>();
    k_round_b0<<<(FIN * H1 + 255) / 256, 256>>>(fc0_w);
    k_build_wc<<<256, 128>>>(czw, chw, lzw, lhw);

    dim3 g1(2, (Nn + 127) / 128);
    k_gemm_tc<128, 0, true><<<g1, 256>>>(x, fc0_b, Nn);     // index 3

    k_build_bc<<<1, 128>>>(czb, chb, lzw, lhw, lzb, lhb);
    k_edge_accum<<<(Ee + 255) / 256, 256>>>(dst, ew);
    k_dinv<<<(Nn + 255) / 256, 256>>>();
    k_scan_block<<<nb, 1024>>>();
    k_scan_sums<<<1, 32>>>(nb);
    k_scan_add<<<nb, 1024>>>();
    k_fill<<<(Ee + 255) / 256, 256>>>(src, dst, ew);

    dim3 g2(2, (Nn + 127) / 128);
    k_gemm_tc<256, 1, false><<<g2, 256>>>(nullptr, nullptr, Nn);

    k_agg_gru<<<Nn, 256>>>(fcw, fcb, hout, out);
}

// round 4
// speedup vs baseline: 1.8881x; 1.0334x over previous
#include <cuda_runtime.h>
#include <math.h>
#include <stdint.h>

#define Nn 100000
#define Ee 800000
#define FIN 128
#define H1  256
#define OUTD 128

// ---------------- scratch (static device globals) ----------------
__device__ float g_Xt[(size_t)Nn * H1];    // rna(relu(x@fc0_w+b))   [N,256] (tf32-rounded)
__device__ float g_G[(size_t)Nn * H1];     // Xt @ Wc                [N,256] (fp32 gates, pre-agg)
__device__ float g_deg[Nn];
__device__ float g_dinv[Nn];
__device__ int   g_count[Nn];
__device__ int   g_rowptr[Nn];
__device__ int   g_cursor[Nn];
__device__ int   g_csr_src[Ee];
__device__ float g_csr_coef[Ee];           // dinv[src]*w
__device__ float g_Wc[H1 * 256];           // combined weights (tf32-rounded), cols interleaved
__device__ float g_bc[256];                // combined bias, interleaved (z,h)
__device__ float g_Wb0[FIN * H1];          // tf32-rounded fc0_w
__device__ int   g_bsums[128];

// ---------------- helpers ----------------
__device__ __forceinline__ float to_tf32(float x) {
    float r;
    asm("cvt.rna.tf32.f32 %0, %1;" : "=f"(r) : "f"(x));
    return r;
}

__device__ __forceinline__ void mma_tf32(float* c, const uint32_t* a, const uint32_t* b) {
    asm volatile(
        "mma.sync.aligned.m16n8k8.row.col.f32.tf32.tf32.f32 "
        "{%0,%1,%2,%3},{%4,%5,%6,%7},{%8,%9},{%0,%1,%2,%3};\n"
        : "+f"(c[0]), "+f"(c[1]), "+f"(c[2]), "+f"(c[3])
        : "r"(a[0]), "r"(a[1]), "r"(a[2]), "r"(a[3]), "r"(b[0]), "r"(b[1]));
}

__device__ __forceinline__ uint32_t smem_u32(const void* p) {
    uint32_t a;
    asm("{ .reg .u64 t; cvta.to.shared.u64 t, %1; cvt.u32.u64 %0, t; }" : "=r"(a) : "l"(p));
    return a;
}

__device__ __forceinline__ void cp_async16(uint32_t dst, const void* src, int szbytes) {
    asm volatile("cp.async.cg.shared.global [%0], [%1], 16, %2;\n"
                 :: "r"(dst), "l"(src), "r"(szbytes));
}
#define CP_COMMIT() asm volatile("cp.async.commit_group;\n" ::: "memory")
#define CP_WAIT1()  asm volatile("cp.async.wait_group 1;\n" ::: "memory")

// ---------------- graph prep ----------------
__global__ void k_init() {
    int i = blockIdx.x * blockDim.x + threadIdx.x;
    if (i < Nn) { g_deg[i] = 1.0f; g_count[i] = 0; g_cursor[i] = 0; }
}

__global__ void k_edge_accum(const int* __restrict__ dst, const float* __restrict__ ew) {
    int e = blockIdx.x * blockDim.x + threadIdx.x;
    if (e < Ee) {
        int d = dst[e];
        atomicAdd(&g_deg[d], ew[e]);
        atomicAdd(&g_count[d], 1);
    }
}

__global__ void k_dinv() {
    int i = blockIdx.x * blockDim.x + threadIdx.x;
    if (i < Nn) g_dinv[i] = rsqrtf(g_deg[i]);
}

__global__ void k_scan_block() {
    __shared__ int s[1024];
    int i = blockIdx.x * 1024 + threadIdx.x;
    int v = (i < Nn) ? g_count[i] : 0;
    s[threadIdx.x] = v;
    __syncthreads();
    #pragma unroll
    for (int off = 1; off < 1024; off <<= 1) {
        int t = (threadIdx.x >= off) ? s[threadIdx.x - off] : 0;
        __syncthreads();
        s[threadIdx.x] += t;
        __syncthreads();
    }
    if (i < Nn) g_rowptr[i] = s[threadIdx.x] - v;
    if (threadIdx.x == 1023) g_bsums[blockIdx.x] = s[1023];
}

__global__ void k_scan_sums(int nb) {
    if (threadIdx.x == 0 && blockIdx.x == 0) {
        int acc = 0;
        for (int b = 0; b < nb; b++) { int t = g_bsums[b]; g_bsums[b] = acc; acc += t; }
    }
}

__global__ void k_scan_add() {
    int i = blockIdx.x * 1024 + threadIdx.x;
    if (i < Nn) g_rowptr[i] += g_bsums[blockIdx.x];
}

__global__ void k_fill(const int* __restrict__ src, const int* __restrict__ dst,
                       const float* __restrict__ ew) {
    int e = blockIdx.x * blockDim.x + threadIdx.x;
    if (e < Ee) {
        int d = dst[e], s = src[e];
        int pos = g_rowptr[d] + atomicAdd(&g_cursor[d], 1);
        g_csr_src[pos]  = s;
        g_csr_coef[pos] = g_dinv[s] * ew[e];
    }
}

// ---------------- weight prep ----------------
__global__ void k_round_b0(const float* __restrict__ w) {
    int i = blockIdx.x * blockDim.x + threadIdx.x;
    if (i < FIN * H1) g_Wb0[i] = to_tf32(w[i]);
}

__global__ void k_build_wc(const float* __restrict__ czw, const float* __restrict__ chw,
                           const float* __restrict__ lzw, const float* __restrict__ lhw) {
    __shared__ float rz[128], rh[128];
    int k = blockIdx.x;
    int j = threadIdx.x;
    rz[j] = czw[k * 128 + j];
    rh[j] = chw[k * 128 + j];
    __syncthreads();
    float az = 0.f, ah = 0.f;
    #pragma unroll 4
    for (int t = 0; t < 128; t++) {
        az += rz[t] * lzw[t * 128 + j];
        ah += rh[t] * lhw[t * 128 + j];
    }
    g_Wc[k * 256 + 2 * j]     = to_tf32(az);
    g_Wc[k * 256 + 2 * j + 1] = to_tf32(ah);
}

__global__ void k_build_bc(const float* __restrict__ czb, const float* __restrict__ chb,
                           const float* __restrict__ lzw, const float* __restrict__ lhw,
                           const float* __restrict__ lzb, const float* __restrict__ lhb) {
    int j = threadIdx.x;
    float az = lzb[j], ah = lhb[j];
    #pragma unroll 4
    for (int t = 0; t < 128; t++) {
        az += czb[t] * lzw[t * 128 + j];
        ah += chb[t] * lhw[t * 128 + j];
    }
    g_bc[2 * j]     = az;
    g_bc[2 * j + 1] = ah;
}

// ---------------- pipelined tf32 tensor-core GEMM, BM=64 x BN=256 ----------------
// C = epi(A[M,K] @ B[K,256]); grid = ceil(M/64) in x only -> A read exactly once.
// EPI 0: relu+bias, tf32-round -> g_Xt. A = x (CVTA), B = g_Wb0.
// EPI 1: raw gates -> g_G. A = g_Xt, B = g_Wc. Bias added post-aggregation.
#define AS_LD 36
#define BS_LD 264
template<int K, int EPI, bool CVTA>
__global__ __launch_bounds__(256, 2) void k_gemm_tc(const float* __restrict__ Ain,
                                                    const float* __restrict__ biasin,
                                                    int M) {
    const float* A    = (EPI == 0) ? Ain   : g_Xt;
    const float* B    = (EPI == 0) ? g_Wb0 : g_Wc;
    float* C          = (EPI == 0) ? g_Xt  : g_G;

    __shared__ float As[2][64 * AS_LD];   // bank(4m+k) conflict-free fragment loads
    __shared__ float Bs[2][32 * BS_LD];   // 264 % 32 == 8 -> bank(8k+n) conflict-free

    const int tid  = threadIdx.x;
    const int lane = tid & 31;
    const int w    = tid >> 5;
    const int wy   = w & 1;               // 2 m-warps of 32 rows
    const int wx   = w >> 1;              // 4 n-warps of 64 cols
    const int g    = lane >> 2;
    const int cq   = lane & 3;

    const int row0  = blockIdx.x * 64;
    const int woffm = wy * 32;
    const int woffn = wx * 64;

    uint32_t sA[2], sB[2];
    sA[0] = smem_u32(&As[0][0]); sA[1] = smem_u32(&As[1][0]);
    sB[0] = smem_u32(&Bs[0][0]); sB[1] = smem_u32(&Bs[1][0]);

    float acc[2][8][4];
    #pragma unroll
    for (int mt = 0; mt < 2; mt++)
        #pragma unroll
        for (int nt = 0; nt < 8; nt++)
            #pragma unroll
            for (int i = 0; i < 4; i++) acc[mt][nt][i] = 0.f;

    auto load_stage = [&](int st, int kb) {
        // A tile: 64x32 = 512 float4 over 256 threads
        #pragma unroll
        for (int l = 0; l < 2; l++) {
            int idx = tid + l * 256;
            int r  = idx >> 3;
            int kc = (idx & 7) << 2;
            int gr = row0 + r;
            int ok = (gr < M);
            const float* gp = A + (size_t)(ok ? gr : (M - 1)) * K + kb + kc;
            cp_async16(sA[st] + (uint32_t)(r * AS_LD + kc) * 4u, gp, ok ? 16 : 0);
        }
        // B tile: 32x256 = 2048 float4 over 256 threads
        #pragma unroll
        for (int l = 0; l < 8; l++) {
            int idx = tid + l * 256;
            int k  = idx >> 6;
            int nc = (idx & 63) << 2;
            cp_async16(sB[st] + (uint32_t)(k * BS_LD + nc) * 4u,
                       B + (size_t)(kb + k) * 256 + nc, 16);
        }
    };

    const int NKB = K / 32;
    load_stage(0, 0);
    CP_COMMIT();

    for (int kbi = 0; kbi < NKB; kbi++) {
        if (kbi + 1 < NKB) load_stage((kbi + 1) & 1, (kbi + 1) * 32);
        CP_COMMIT();
        CP_WAIT1();
        __syncthreads();
        const float* as = As[kbi & 1];
        const float* bs = Bs[kbi & 1];

        #pragma unroll
        for (int kk = 0; kk < 32; kk += 8) {
            uint32_t af[2][4], bf[8][2];
            #pragma unroll
            for (int mt = 0; mt < 2; mt++) {
                int mb = woffm + mt * 16;
                float a0 = as[(mb + g)     * AS_LD + kk + cq];
                float a1 = as[(mb + g + 8) * AS_LD + kk + cq];
                float a2 = as[(mb + g)     * AS_LD + kk + cq + 4];
                float a3 = as[(mb + g + 8) * AS_LD + kk + cq + 4];
                if (CVTA) { a0 = to_tf32(a0); a1 = to_tf32(a1); a2 = to_tf32(a2); a3 = to_tf32(a3); }
                af[mt][0] = __float_as_uint(a0); af[mt][1] = __float_as_uint(a1);
                af[mt][2] = __float_as_uint(a2); af[mt][3] = __float_as_uint(a3);
            }
            #pragma unroll
            for (int nt = 0; nt < 8; nt++) {
                int n = woffn + nt * 8 + g;
                bf[nt][0] = __float_as_uint(bs[(kk + cq)     * BS_LD + n]);
                bf[nt][1] = __float_as_uint(bs[(kk + cq + 4) * BS_LD + n]);
            }
            #pragma unroll
            for (int mt = 0; mt < 2; mt++)
                #pragma unroll
                for (int nt = 0; nt < 8; nt++)
                    mma_tf32(acc[mt][nt], af[mt], bf[nt]);
        }
        __syncthreads();
    }

    // epilogue — frag c0:(g, 2cq), c1:(g, 2cq+1), c2:(g+8, 2cq), c3:(g+8, 2cq+1)
    #pragma unroll
    for (int mt = 0; mt < 2; mt++) {
        int r0 = row0 + woffm + mt * 16 + g;
        int r1 = r0 + 8;
        #pragma unroll
        for (int nt = 0; nt < 8; nt++) {
            int col = woffn + nt * 8 + 2 * cq;
            if (EPI == 0) {
                float b0 = biasin[col], b1 = biasin[col + 1];
                if (r0 < M) {
                    float2 o = make_float2(to_tf32(fmaxf(acc[mt][nt][0] + b0, 0.f)),
                                           to_tf32(fmaxf(acc[mt][nt][1] + b1, 0.f)));
                    *(float2*)(C + (size_t)r0 * 256 + col) = o;
                }
                if (r1 < M) {
                    float2 o = make_float2(to_tf32(fmaxf(acc[mt][nt][2] + b0, 0.f)),
                                           to_tf32(fmaxf(acc[mt][nt][3] + b1, 0.f)));
                    *(float2*)(C + (size_t)r1 * 256 + col) = o;
                }
            } else {
                if (r0 < M)
                    *(float2*)(C + (size_t)r0 * 256 + col) = make_float2(acc[mt][nt][0], acc[mt][nt][1]);
                if (r1 < M)
                    *(float2*)(C + (size_t)r1 * 256 + col) = make_float2(acc[mt][nt][2], acc[mt][nt][3]);
            }
        }
    }
}

// ---------------- fused aggregate + bias + GRU + output head, feature-split ----------------
// PASS p handles global gate features [128p, 128p+128) = h columns [64p, 64p+64).
// Per-pass touched G lines = 51 MB -> L2-resident gathers.
__global__ __launch_bounds__(128) void k_agg_gru(const float* __restrict__ fcw,
                                                 const float* __restrict__ fcb,
                                                 float* __restrict__ hout,
                                                 float* __restrict__ out,
                                                 int PASS) {
    __shared__ float s_red[4];
    int d = blockIdx.x;
    int t = threadIdx.x;                 // 0..127
    int fg = PASS * 128 + t;             // global interleaved gate index
    size_t off = (size_t)PASS * 128 + t;
    float di = g_dinv[d];

    float gself = g_G[(size_t)d * 256 + off];
    float a0 = gself, a1 = 0.f, a2 = 0.f, a3 = 0.f;

    int e = g_rowptr[d], end = e + g_count[d];
    for (; e + 4 <= end; e += 4) {
        int   s0 = g_csr_src[e],     s1 = g_csr_src[e + 1];
        int   s2 = g_csr_src[e + 2], s3 = g_csr_src[e + 3];
        float c0 = g_csr_coef[e],     c1 = g_csr_coef[e + 1];
        float c2 = g_csr_coef[e + 2], c3 = g_csr_coef[e + 3];
        a0 += c0 * g_G[(size_t)s0 * 256 + off];
        a1 += c1 * g_G[(size_t)s1 * 256 + off];
        a2 += c2 * g_G[(size_t)s2 * 256 + off];
        a3 += c3 * g_G[(size_t)s3 * 256 + off];
    }
    for (; e < end; e++)
        a0 += g_csr_coef[e] * g_G[(size_t)g_csr_src[e] * 256 + off];

    float gate = ((a0 + a1) + (a2 + a3)) * di + (di * di - di) * gself + g_bc[fg];

    float other = __shfl_xor_sync(0xffffffffu, gate, 1);
    float prod = 0.f;
    if ((t & 1) == 0) {
        float z = 1.f / (1.f + expf(-gate));
        float h = (1.f - z) * tanhf(other);
        hout[(size_t)d * 128 + (fg >> 1)] = h;
        prod = fmaxf(h, 0.f) * fcw[fg >> 1];
    }
    #pragma unroll
    for (int o = 16; o; o >>= 1) prod += __shfl_xor_sync(0xffffffffu, prod, o);
    if ((t & 31) == 0) s_red[t >> 5] = prod;
    __syncthreads();
    if (t == 0) {
        float s = (s_red[0] + s_red[1]) + (s_red[2] + s_red[3]);
        if (PASS == 0) out[d] = s + fcb[0];
        else           out[d] += s;
    }
}

// ---------------- launch ----------------
extern "C" void kernel_launch(void* const* d_in, const int* in_sizes, int n_in,
                              void* d_out, int out_size) {
    const float* x     = (const float*)d_in[0];
    const int*   ei    = (const int*)d_in[1];
    const float* ew    = (const float*)d_in[2];
    const float* fc0_w = (const float*)d_in[3];
    const float* fc0_b = (const float*)d_in[4];
    // d_in[5] = att: softmax over one element == 1.0
    const float* czw   = (const float*)d_in[6];
    const float* czb   = (const float*)d_in[7];
    const float* lzw   = (const float*)d_in[8];
    const float* lzb   = (const float*)d_in[9];
    // d_in[10..13] dead (H0 == 0 kills the R branch)
    const float* chw   = (const float*)d_in[14];
    const float* chb   = (const float*)d_in[15];
    const float* lhw   = (const float*)d_in[16];
    const float* lhb   = (const float*)d_in[17];
    const float* fcw   = (const float*)d_in[18];
    const float* fcb   = (const float*)d_in[19];

    const int* src = ei;
    const int* dst = ei + Ee;

    float* out  = (float*)d_out;
    float* hout = out + Nn;

    const int nb = (Nn + 1023) / 1024;
    const int gM = (Nn + 63) / 64;

    // keep GEMM1 at launch index 3 (ncu capture slot)
    k_init<<<(Nn + 255) / 256, 256>>>();
    k_round_b0<<<(FIN * H1 + 255) / 256, 256>>>(fc0_w);
    k_build_wc<<<256, 128>>>(czw, chw, lzw, lhw);

    k_gemm_tc<128, 0, true><<<gM, 256>>>(x, fc0_b, Nn);     // index 3

    k_build_bc<<<1, 128>>>(czb, chb, lzw, lhw, lzb, lhb);
    k_edge_accum<<<(Ee + 255) / 256, 256>>>(dst, ew);
    k_dinv<<<(Nn + 255) / 256, 256>>>();
    k_scan_block<<<nb, 1024>>>();
    k_scan_sums<<<1, 32>>>(nb);
    k_scan_add<<<nb, 1024>>>();
    k_fill<<<(Ee + 255) / 256, 256>>>(src, dst, ew);

    k_gemm_tc<256, 1, false><<<gM, 256>>>(nullptr, nullptr, Nn);

    k_agg_gru<<<Nn, 128>>>(fcw, fcb, hout, out, 0);
    k_agg_gru<<<Nn, 128>>>(fcw, fcb, hout, out, 1);
}

// round 5
// speedup vs baseline: 2.0060x; 1.0624x over previous
#include <cuda_runtime.h>
#include <math.h>
#include <stdint.h>

#define Nn 100000
#define Ee 800000
#define FIN 128
#define H1  256
#define OUTD 128

// ---------------- scratch (static device globals) ----------------
__device__ float g_Xt[(size_t)Nn * H1];    // rna(relu(x@fc0_w+b))   [N,256] (tf32-rounded)
__device__ float g_G[(size_t)Nn * H1];     // Xt @ Wc                [N,256] (fp32 gates, pre-agg)
__device__ float g_deg[Nn];
__device__ float g_dinv[Nn];
__device__ int   g_count[Nn];
__device__ int   g_rowptr[Nn];
__device__ int   g_cursor[Nn];
__device__ int2  g_csr[Ee];                // {src, __float_as_int(dinv[src]*w)}
__device__ float g_Wc[H1 * 256];           // combined weights (tf32-rounded), cols interleaved
__device__ float g_bc[256];                // combined bias, interleaved (z,h)
__device__ float g_Wb0[FIN * H1];          // tf32-rounded fc0_w
__device__ int   g_bsums[128];

// ---------------- helpers ----------------
__device__ __forceinline__ float to_tf32(float x) {
    float r;
    asm("cvt.rna.tf32.f32 %0, %1;" : "=f"(r) : "f"(x));
    return r;
}

__device__ __forceinline__ void mma_tf32(float* c, const uint32_t* a, const uint32_t* b) {
    asm volatile(
        "mma.sync.aligned.m16n8k8.row.col.f32.tf32.tf32.f32 "
        "{%0,%1,%2,%3},{%4,%5,%6,%7},{%8,%9},{%0,%1,%2,%3};\n"
        : "+f"(c[0]), "+f"(c[1]), "+f"(c[2]), "+f"(c[3])
        : "r"(a[0]), "r"(a[1]), "r"(a[2]), "r"(a[3]), "r"(b[0]), "r"(b[1]));
}

__device__ __forceinline__ uint32_t smem_u32(const void* p) {
    uint32_t a;
    asm("{ .reg .u64 t; cvta.to.shared.u64 t, %1; cvt.u32.u64 %0, t; }" : "=r"(a) : "l"(p));
    return a;
}

__device__ __forceinline__ void cp_async16(uint32_t dst, const void* src, int szbytes) {
    asm volatile("cp.async.cg.shared.global [%0], [%1], 16, %2;\n"
                 :: "r"(dst), "l"(src), "r"(szbytes));
}
#define CP_COMMIT() asm volatile("cp.async.commit_group;\n" ::: "memory")
#define CP_WAIT1()  asm volatile("cp.async.wait_group 1;\n" ::: "memory")

// ---------------- graph prep ----------------
__global__ void k_init() {
    int i = blockIdx.x * blockDim.x + threadIdx.x;
    if (i < Nn) { g_deg[i] = 1.0f; g_count[i] = 0; g_cursor[i] = 0; }
}

__global__ void k_edge_accum(const int* __restrict__ dst, const float* __restrict__ ew) {
    int e = blockIdx.x * blockDim.x + threadIdx.x;
    if (e < Ee) {
        int d = dst[e];
        atomicAdd(&g_deg[d], ew[e]);
        atomicAdd(&g_count[d], 1);
    }
}

__global__ void k_dinv() {
    int i = blockIdx.x * blockDim.x + threadIdx.x;
    if (i < Nn) g_dinv[i] = rsqrtf(g_deg[i]);
}

__global__ void k_scan_block() {
    __shared__ int s[1024];
    int i = blockIdx.x * 1024 + threadIdx.x;
    int v = (i < Nn) ? g_count[i] : 0;
    s[threadIdx.x] = v;
    __syncthreads();
    #pragma unroll
    for (int off = 1; off < 1024; off <<= 1) {
        int t = (threadIdx.x >= off) ? s[threadIdx.x - off] : 0;
        __syncthreads();
        s[threadIdx.x] += t;
        __syncthreads();
    }
    if (i < Nn) g_rowptr[i] = s[threadIdx.x] - v;
    if (threadIdx.x == 1023) g_bsums[blockIdx.x] = s[1023];
}

__global__ void k_scan_sums(int nb) {
    if (threadIdx.x == 0 && blockIdx.x == 0) {
        int acc = 0;
        for (int b = 0; b < nb; b++) { int t = g_bsums[b]; g_bsums[b] = acc; acc += t; }
    }
}

__global__ void k_scan_add() {
    int i = blockIdx.x * 1024 + threadIdx.x;
    if (i < Nn) g_rowptr[i] += g_bsums[blockIdx.x];
}

__global__ void k_fill(const int* __restrict__ src, const int* __restrict__ dst,
                       const float* __restrict__ ew) {
    int e = blockIdx.x * blockDim.x + threadIdx.x;
    if (e < Ee) {
        int d = dst[e], s = src[e];
        int pos = g_rowptr[d] + atomicAdd(&g_cursor[d], 1);
        g_csr[pos] = make_int2(s, __float_as_int(g_dinv[s] * ew[e]));
    }
}

// ---------------- weight prep ----------------
__global__ void k_round_b0(const float* __restrict__ w) {
    int i = blockIdx.x * blockDim.x + threadIdx.x;
    if (i < FIN * H1) g_Wb0[i] = to_tf32(w[i]);
}

__global__ void k_build_wc(const float* __restrict__ czw, const float* __restrict__ chw,
                           const float* __restrict__ lzw, const float* __restrict__ lhw) {
    __shared__ float rz[128], rh[128];
    int k = blockIdx.x;
    int j = threadIdx.x;
    rz[j] = czw[k * 128 + j];
    rh[j] = chw[k * 128 + j];
    __syncthreads();
    float az = 0.f, ah = 0.f;
    #pragma unroll 4
    for (int t = 0; t < 128; t++) {
        az += rz[t] * lzw[t * 128 + j];
        ah += rh[t] * lhw[t * 128 + j];
    }
    g_Wc[k * 256 + 2 * j]     = to_tf32(az);
    g_Wc[k * 256 + 2 * j + 1] = to_tf32(ah);
}

__global__ void k_build_bc(const float* __restrict__ czb, const float* __restrict__ chb,
                           const float* __restrict__ lzw, const float* __restrict__ lhw,
                           const float* __restrict__ lzb, const float* __restrict__ lhb) {
    int j = threadIdx.x;
    float az = lzb[j], ah = lhb[j];
    #pragma unroll 4
    for (int t = 0; t < 128; t++) {
        az += czb[t] * lzw[t * 128 + j];
        ah += chb[t] * lhw[t * 128 + j];
    }
    g_bc[2 * j]     = az;
    g_bc[2 * j + 1] = ah;
}

// ---------------- pipelined tf32 tensor-core GEMM, BM=64 x BN=256 ----------------
#define AS_LD 36
#define BS_LD 264
template<int K, int EPI, bool CVTA>
__global__ __launch_bounds__(256, 2) void k_gemm_tc(const float* __restrict__ Ain,
                                                    const float* __restrict__ biasin,
                                                    int M) {
    const float* A    = (EPI == 0) ? Ain   : g_Xt;
    const float* B    = (EPI == 0) ? g_Wb0 : g_Wc;
    float* C          = (EPI == 0) ? g_Xt  : g_G;

    __shared__ float As[2][64 * AS_LD];
    __shared__ float Bs[2][32 * BS_LD];

    const int tid  = threadIdx.x;
    const int lane = tid & 31;
    const int w    = tid >> 5;
    const int wy   = w & 1;
    const int wx   = w >> 1;
    const int g    = lane >> 2;
    const int cq   = lane & 3;

    const int row0  = blockIdx.x * 64;
    const int woffm = wy * 32;
    const int woffn = wx * 64;

    uint32_t sA[2], sB[2];
    sA[0] = smem_u32(&As[0][0]); sA[1] = smem_u32(&As[1][0]);
    sB[0] = smem_u32(&Bs[0][0]); sB[1] = smem_u32(&Bs[1][0]);

    float acc[2][8][4];
    #pragma unroll
    for (int mt = 0; mt < 2; mt++)
        #pragma unroll
        for (int nt = 0; nt < 8; nt++)
            #pragma unroll
            for (int i = 0; i < 4; i++) acc[mt][nt][i] = 0.f;

    auto load_stage = [&](int st, int kb) {
        #pragma unroll
        for (int l = 0; l < 2; l++) {
            int idx = tid + l * 256;
            int r  = idx >> 3;
            int kc = (idx & 7) << 2;
            int gr = row0 + r;
            int ok = (gr < M);
            const float* gp = A + (size_t)(ok ? gr : (M - 1)) * K + kb + kc;
            cp_async16(sA[st] + (uint32_t)(r * AS_LD + kc) * 4u, gp, ok ? 16 : 0);
        }
        #pragma unroll
        for (int l = 0; l < 8; l++) {
            int idx = tid + l * 256;
            int k  = idx >> 6;
            int nc = (idx & 63) << 2;
            cp_async16(sB[st] + (uint32_t)(k * BS_LD + nc) * 4u,
                       B + (size_t)(kb + k) * 256 + nc, 16);
        }
    };

    const int NKB = K / 32;
    load_stage(0, 0);
    CP_COMMIT();

    for (int kbi = 0; kbi < NKB; kbi++) {
        if (kbi + 1 < NKB) load_stage((kbi + 1) & 1, (kbi + 1) * 32);
        CP_COMMIT();
        CP_WAIT1();
        __syncthreads();
        const float* as = As[kbi & 1];
        const float* bs = Bs[kbi & 1];

        #pragma unroll
        for (int kk = 0; kk < 32; kk += 8) {
            uint32_t af[2][4], bf[8][2];
            #pragma unroll
            for (int mt = 0; mt < 2; mt++) {
                int mb = woffm + mt * 16;
                float a0 = as[(mb + g)     * AS_LD + kk + cq];
                float a1 = as[(mb + g + 8) * AS_LD + kk + cq];
                float a2 = as[(mb + g)     * AS_LD + kk + cq + 4];
                float a3 = as[(mb + g + 8) * AS_LD + kk + cq + 4];
                if (CVTA) { a0 = to_tf32(a0); a1 = to_tf32(a1); a2 = to_tf32(a2); a3 = to_tf32(a3); }
                af[mt][0] = __float_as_uint(a0); af[mt][1] = __float_as_uint(a1);
                af[mt][2] = __float_as_uint(a2); af[mt][3] = __float_as_uint(a3);
            }
            #pragma unroll
            for (int nt = 0; nt < 8; nt++) {
                int n = woffn + nt * 8 + g;
                bf[nt][0] = __float_as_uint(bs[(kk + cq)     * BS_LD + n]);
                bf[nt][1] = __float_as_uint(bs[(kk + cq + 4) * BS_LD + n]);
            }
            #pragma unroll
            for (int mt = 0; mt < 2; mt++)
                #pragma unroll
                for (int nt = 0; nt < 8; nt++)
                    mma_tf32(acc[mt][nt], af[mt], bf[nt]);
        }
        __syncthreads();
    }

    #pragma unroll
    for (int mt = 0; mt < 2; mt++) {
        int r0 = row0 + woffm + mt * 16 + g;
        int r1 = r0 + 8;
        #pragma unroll
        for (int nt = 0; nt < 8; nt++) {
            int col = woffn + nt * 8 + 2 * cq;
            if (EPI == 0) {
                float b0 = biasin[col], b1 = biasin[col + 1];
                if (r0 < M) {
                    float2 o = make_float2(to_tf32(fmaxf(acc[mt][nt][0] + b0, 0.f)),
                                           to_tf32(fmaxf(acc[mt][nt][1] + b1, 0.f)));
                    *(float2*)(C + (size_t)r0 * 256 + col) = o;
                }
                if (r1 < M) {
                    float2 o = make_float2(to_tf32(fmaxf(acc[mt][nt][2] + b0, 0.f)),
                                           to_tf32(fmaxf(acc[mt][nt][3] + b1, 0.f)));
                    *(float2*)(C + (size_t)r1 * 256 + col) = o;
                }
            } else {
                if (r0 < M)
                    *(float2*)(C + (size_t)r0 * 256 + col) = make_float2(acc[mt][nt][0], acc[mt][nt][1]);
                if (r1 < M)
                    *(float2*)(C + (size_t)r1 * 256 + col) = make_float2(acc[mt][nt][2], acc[mt][nt][3]);
            }
        }
    }
}

// ---------------- fused aggregate + bias + GRU + output head ----------------
// Warp-per-edge: each warp gathers a full 128-feature (512 B) slice with one
// LDG.128 per lane; 4 warps process 4 edges concurrently, unrolled x2.
// PASS p covers gate features [128p, 128p+128) = h columns [64p, 64p+64).
__global__ __launch_bounds__(128) void k_agg_gru(const float* __restrict__ fcw,
                                                 const float* __restrict__ fcb,
                                                 float* __restrict__ hout,
                                                 float* __restrict__ out,
                                                 int PASS) {
    __shared__ float4 s_part[4][32];
    __shared__ float s_red[4];
    const int d    = blockIdx.x;
    const int t    = threadIdx.x;      // 0..127
    const int wid  = t >> 5;
    const int lane = t & 31;

    const float4* G4 = (const float4*)g_G;          // row stride 64 float4
    const size_t coloff = (size_t)PASS * 32 + lane; // float4 col in row

    float4 acc = make_float4(0.f, 0.f, 0.f, 0.f);
    const int beg = g_rowptr[d];
    const int end = beg + g_count[d];

    int e = beg + wid;
    for (; e + 4 < end; e += 8) {
        int2 p0 = g_csr[e];
        int2 p1 = g_csr[e + 4];
        float c0 = __int_as_float(p0.y);
        float c1 = __int_as_float(p1.y);
        float4 v0 = G4[(size_t)p0.x * 64 + coloff];
        float4 v1 = G4[(size_t)p1.x * 64 + coloff];
        acc.x += c0 * v0.x + c1 * v1.x;
        acc.y += c0 * v0.y + c1 * v1.y;
        acc.z += c0 * v0.z + c1 * v1.z;
        acc.w += c0 * v0.w + c1 * v1.w;
    }
    if (e < end) {
        int2 p0 = g_csr[e];
        float c0 = __int_as_float(p0.y);
        float4 v0 = G4[(size_t)p0.x * 64 + coloff];
        acc.x += c0 * v0.x; acc.y += c0 * v0.y;
        acc.z += c0 * v0.z; acc.w += c0 * v0.w;
    }
    s_part[wid][lane] = acc;
    __syncthreads();

    // thread t owns gate feature t of this pass's slice
    const int f4 = t >> 2, fc = t & 3;
    float sum = 0.f;
    #pragma unroll
    for (int w = 0; w < 4; w++)
        sum += ((const float*)&s_part[w][f4])[fc];

    const float di = g_dinv[d];
    const int fg = PASS * 128 + t;
    const float gself = g_G[(size_t)d * 256 + fg];
    float gate = sum * di + (di * di) * gself + g_bc[fg];

    float other = __shfl_xor_sync(0xffffffffu, gate, 1);
    float prod = 0.f;
    if ((t & 1) == 0) {
        float z = 1.f / (1.f + expf(-gate));
        float h = (1.f - z) * tanhf(other);
        hout[(size_t)d * 128 + (fg >> 1)] = h;
        prod = fmaxf(h, 0.f) * fcw[fg >> 1];
    }
    #pragma unroll
    for (int o = 16; o; o >>= 1) prod += __shfl_xor_sync(0xffffffffu, prod, o);
    if (lane == 0) s_red[wid] = prod;
    __syncthreads();
    if (t == 0) {
        float s = (s_red[0] + s_red[1]) + (s_red[2] + s_red[3]);
        if (PASS == 0) out[d] = s + fcb[0];
        else           out[d] += s;
    }
}

// ---------------- launch ----------------
extern "C" void kernel_launch(void* const* d_in, const int* in_sizes, int n_in,
                              void* d_out, int out_size) {
    const float* x     = (const float*)d_in[0];
    const int*   ei    = (const int*)d_in[1];
    const float* ew    = (const float*)d_in[2];
    const float* fc0_w = (const float*)d_in[3];
    const float* fc0_b = (const float*)d_in[4];
    // d_in[5] = att: softmax over one element == 1.0
    const float* czw   = (const float*)d_in[6];
    const float* czb   = (const float*)d_in[7];
    const float* lzw   = (const float*)d_in[8];
    const float* lzb   = (const float*)d_in[9];
    // d_in[10..13] dead (H0 == 0 kills the R branch)
    const float* chw   = (const float*)d_in[14];
    const float* chb   = (const float*)d_in[15];
    const float* lhw   = (const float*)d_in[16];
    const float* lhb   = (const float*)d_in[17];
    const float* fcw   = (const float*)d_in[18];
    const float* fcb   = (const float*)d_in[19];

    const int* src = ei;
    const int* dst = ei + Ee;

    float* out  = (float*)d_out;
    float* hout = out + Nn;

    const int nb = (Nn + 1023) / 1024;
    const int gM = (Nn + 63) / 64;

    // keep GEMM1 at launch index 3 (ncu capture slot, control)
    k_init<<<(Nn + 255) / 256, 256>>>();
    k_round_b0<<<(FIN * H1 + 255) / 256, 256>>>(fc0_w);
    k_build_wc<<<256, 128>>>(czw, chw, lzw, lhw);

    k_gemm_tc<128, 0, true><<<gM, 256>>>(x, fc0_b, Nn);     // index 3

    k_build_bc<<<1, 128>>>(czb, chb, lzw, lhw, lzb, lhb);
    k_edge_accum<<<(Ee + 255) / 256, 256>>>(dst, ew);
    k_dinv<<<(Nn + 255) / 256, 256>>>();
    k_scan_block<<<nb, 1024>>>();
    k_scan_sums<<<1, 32>>>(nb);
    k_scan_add<<<nb, 1024>>>();
    k_fill<<<(Ee + 255) / 256, 256>>>(src, dst, ew);

    k_gemm_tc<256, 1, false><<<gM, 256>>>(nullptr, nullptr, Nn);

    k_agg_gru<<<Nn, 128>>>(fcw, fcb, hout, out, 0);
    k_agg_gru<<<Nn, 128>>>(fcw, fcb, hout, out, 1);
}

// round 6
// speedup vs baseline: 3.0091x; 1.5000x over previous
#include <cuda_runtime.h>
#include <math.h>
#include <stdint.h>

#define Nn 100000
#define Ee 800000
#define FIN 128
#define H1  256
#define OUTD 128

// ---------------- scratch (static device globals) ----------------
__device__ float g_G[(size_t)Nn * H1];     // fused GEMM output: gates pre-aggregation [N,256]
__device__ float g_deg[Nn];
__device__ float g_dinv[Nn];
__device__ int   g_count[Nn];
__device__ int   g_rowptr[Nn];
__device__ int   g_cursor[Nn];
__device__ int2  g_csr[Ee];                // {src, __float_as_int(dinv[src]*w)}
__device__ float g_Wc[H1 * 256];           // folded weights (tf32), cols interleaved (z,h)
__device__ float g_bc[256];                // folded bias, interleaved
__device__ float g_Wb0[FIN * H1];          // tf32-rounded fc0_w
__device__ int   g_bsums[128];

// ---------------- helpers ----------------
__device__ __forceinline__ float to_tf32(float x) {
    float r;
    asm("cvt.rna.tf32.f32 %0, %1;" : "=f"(r) : "f"(x));
    return r;
}

__device__ __forceinline__ void mma_tf32(float* c, const uint32_t* a, const uint32_t* b) {
    asm volatile(
        "mma.sync.aligned.m16n8k8.row.col.f32.tf32.tf32.f32 "
        "{%0,%1,%2,%3},{%4,%5,%6,%7},{%8,%9},{%0,%1,%2,%3};\n"
        : "+f"(c[0]), "+f"(c[1]), "+f"(c[2]), "+f"(c[3])
        : "r"(a[0]), "r"(a[1]), "r"(a[2]), "r"(a[3]), "r"(b[0]), "r"(b[1]));
}

__device__ __forceinline__ uint32_t smem_u32(const void* p) {
    uint32_t a;
    asm("{ .reg .u64 t; cvta.to.shared.u64 t, %1; cvt.u32.u64 %0, t; }" : "=r"(a) : "l"(p));
    return a;
}

__device__ __forceinline__ void cp_async16(uint32_t dst, const void* src, int szbytes) {
    asm volatile("cp.async.cg.shared.global [%0], [%1], 16, %2;\n"
                 :: "r"(dst), "l"(src), "r"(szbytes));
}
#define CP_COMMIT() asm volatile("cp.async.commit_group;\n" ::: "memory")
#define CP_WAIT1()  asm volatile("cp.async.wait_group 1;\n" ::: "memory")

// ---------------- graph prep ----------------
__global__ void k_init() {
    int i = blockIdx.x * blockDim.x + threadIdx.x;
    if (i < Nn) { g_deg[i] = 1.0f; g_count[i] = 0; g_cursor[i] = 0; }
}

__global__ void k_edge_accum(const int* __restrict__ dst, const float* __restrict__ ew) {
    int e = blockIdx.x * blockDim.x + threadIdx.x;
    if (e < Ee) {
        int d = dst[e];
        atomicAdd(&g_deg[d], ew[e]);
        atomicAdd(&g_count[d], 1);
    }
}

__global__ void k_dinv() {
    int i = blockIdx.x * blockDim.x + threadIdx.x;
    if (i < Nn) g_dinv[i] = rsqrtf(g_deg[i]);
}

__global__ void k_scan_block() {
    __shared__ int s[1024];
    int i = blockIdx.x * 1024 + threadIdx.x;
    int v = (i < Nn) ? g_count[i] : 0;
    s[threadIdx.x] = v;
    __syncthreads();
    #pragma unroll
    for (int off = 1; off < 1024; off <<= 1) {
        int t = (threadIdx.x >= off) ? s[threadIdx.x - off] : 0;
        __syncthreads();
        s[threadIdx.x] += t;
        __syncthreads();
    }
    if (i < Nn) g_rowptr[i] = s[threadIdx.x] - v;
    if (threadIdx.x == 1023) g_bsums[blockIdx.x] = s[1023];
}

__global__ void k_scan_sums(int nb) {
    if (threadIdx.x == 0 && blockIdx.x == 0) {
        int acc = 0;
        for (int b = 0; b < nb; b++) { int t = g_bsums[b]; g_bsums[b] = acc; acc += t; }
    }
}

__global__ void k_scan_add() {
    int i = blockIdx.x * 1024 + threadIdx.x;
    if (i < Nn) g_rowptr[i] += g_bsums[blockIdx.x];
}

__global__ void k_fill(const int* __restrict__ src, const int* __restrict__ dst,
                       const float* __restrict__ ew) {
    int e = blockIdx.x * blockDim.x + threadIdx.x;
    if (e < Ee) {
        int d = dst[e], s = src[e];
        int pos = g_rowptr[d] + atomicAdd(&g_cursor[d], 1);
        g_csr[pos] = make_int2(s, __float_as_int(g_dinv[s] * ew[e]));
    }
}

// ---------------- weight prep ----------------
__global__ void k_round_b0(const float* __restrict__ w) {
    int i = blockIdx.x * blockDim.x + threadIdx.x;
    if (i < FIN * H1) g_Wb0[i] = to_tf32(w[i]);
}

__global__ void k_build_wc(const float* __restrict__ czw, const float* __restrict__ chw,
                           const float* __restrict__ lzw, const float* __restrict__ lhw) {
    __shared__ float rz[128], rh[128];
    int k = blockIdx.x;
    int j = threadIdx.x;
    rz[j] = czw[k * 128 + j];
    rh[j] = chw[k * 128 + j];
    __syncthreads();
    float az = 0.f, ah = 0.f;
    #pragma unroll 4
    for (int t = 0; t < 128; t++) {
        az += rz[t] * lzw[t * 128 + j];
        ah += rh[t] * lhw[t * 128 + j];
    }
    g_Wc[k * 256 + 2 * j]     = to_tf32(az);
    g_Wc[k * 256 + 2 * j + 1] = to_tf32(ah);
}

__global__ void k_build_bc(const float* __restrict__ czb, const float* __restrict__ chb,
                           const float* __restrict__ lzw, const float* __restrict__ lhw,
                           const float* __restrict__ lzb, const float* __restrict__ lhb) {
    int j = threadIdx.x;
    float az = lzb[j], ah = lhb[j];
    #pragma unroll 4
    for (int t = 0; t < 128; t++) {
        az += czb[t] * lzw[t * 128 + j];
        ah += chb[t] * lhw[t * 128 + j];
    }
    g_bc[2 * j]     = az;
    g_bc[2 * j + 1] = ah;
}

// ---------------- fused double-GEMM: G = rna(relu(x@W0+b)) @ Wc ----------------
// BM=64, BN=256, 8 warps (warp tile 32x64).
// Stage A: K=128 from x (cvt to tf32 at fragment load), epilogue -> smem As2.
// Stage B: K=256 from As2 (A) x g_Wc streamed (B, double-buffered 16-k tiles) -> g_G raw.
// smem layout (floats): As2 [0,16640) stride 260; stage-A Asa [0,4608) dbl 64x36,
// Bsa [4608,21504) dbl 32x264 (dead before As2 written); Bsb [16640,25088) dbl 16x264.
#define ASA_OFF 0
#define ASA_SZ  (64 * 36)
#define BSA_OFF 4608
#define BSA_SZ  (32 * 264)
#define AS2_OFF 0
#define AS2_LD  260
#define BSB_OFF 16640
#define BSB_SZ  (16 * 264)
#define SMEM_FLOATS 25088

__global__ __launch_bounds__(256, 2) void k_gemm_fused(const float* __restrict__ x,
                                                       const float* __restrict__ bias0,
                                                       int M) {
    extern __shared__ float sm[];

    const int tid  = threadIdx.x;
    const int lane = tid & 31;
    const int w    = tid >> 5;
    const int wy   = w & 1;
    const int wx   = w >> 1;
    const int g    = lane >> 2;
    const int cq   = lane & 3;

    const int row0  = blockIdx.x * 64;
    const int woffm = wy * 32;
    const int woffn = wx * 64;

    const uint32_t smb = smem_u32(sm);

    float acc[2][8][4];
    #pragma unroll
    for (int mt = 0; mt < 2; mt++)
        #pragma unroll
        for (int nt = 0; nt < 8; nt++)
            #pragma unroll
            for (int i = 0; i < 4; i++) acc[mt][nt][i] = 0.f;

    // ---- stage A: Xt_tile = relu(x[row0:row0+64, :] @ W0 + b), K=128 ----
    auto load_a = [&](int st, int kb) {
        #pragma unroll
        for (int l = 0; l < 2; l++) {
            int idx = tid + l * 256;
            int r  = idx >> 3;
            int kc = (idx & 7) << 2;
            int gr = row0 + r;
            int ok = (gr < M);
            const float* gp = x + (size_t)(ok ? gr : (M - 1)) * FIN + kb + kc;
            cp_async16(smb + (uint32_t)(ASA_OFF + st * ASA_SZ + r * 36 + kc) * 4u, gp, ok ? 16 : 0);
        }
        #pragma unroll
        for (int l = 0; l < 8; l++) {
            int idx = tid + l * 256;
            int k  = idx >> 6;
            int nc = (idx & 63) << 2;
            cp_async16(smb + (uint32_t)(BSA_OFF + st * BSA_SZ + k * 264 + nc) * 4u,
                       g_Wb0 + (size_t)(kb + k) * 256 + nc, 16);
        }
    };

    load_a(0, 0);
    CP_COMMIT();

    for (int kbi = 0; kbi < 4; kbi++) {
        if (kbi + 1 < 4) load_a((kbi + 1) & 1, (kbi + 1) * 32);
        CP_COMMIT();
        CP_WAIT1();
        __syncthreads();
        const float* as = sm + ASA_OFF + (kbi & 1) * ASA_SZ;
        const float* bs = sm + BSA_OFF + (kbi & 1) * BSA_SZ;

        #pragma unroll
        for (int kk = 0; kk < 32; kk += 8) {
            uint32_t af[2][4], bf[8][2];
            #pragma unroll
            for (int mt = 0; mt < 2; mt++) {
                int mb = woffm + mt * 16;
                af[mt][0] = __float_as_uint(to_tf32(as[(mb + g)     * 36 + kk + cq]));
                af[mt][1] = __float_as_uint(to_tf32(as[(mb + g + 8) * 36 + kk + cq]));
                af[mt][2] = __float_as_uint(to_tf32(as[(mb + g)     * 36 + kk + cq + 4]));
                af[mt][3] = __float_as_uint(to_tf32(as[(mb + g + 8) * 36 + kk + cq + 4]));
            }
            #pragma unroll
            for (int nt = 0; nt < 8; nt++) {
                int n = woffn + nt * 8 + g;
                bf[nt][0] = __float_as_uint(bs[(kk + cq)     * 264 + n]);
                bf[nt][1] = __float_as_uint(bs[(kk + cq + 4) * 264 + n]);
            }
            #pragma unroll
            for (int mt = 0; mt < 2; mt++)
                #pragma unroll
                for (int nt = 0; nt < 8; nt++)
                    mma_tf32(acc[mt][nt], af[mt], bf[nt]);
        }
        __syncthreads();
    }

    // stage-A epilogue: relu + bias + tf32-round, into As2 (local rows 0..63)
    #pragma unroll
    for (int mt = 0; mt < 2; mt++) {
        int r0 = woffm + mt * 16 + g;
        int r1 = r0 + 8;
        #pragma unroll
        for (int nt = 0; nt < 8; nt++) {
            int col = woffn + nt * 8 + 2 * cq;
            float b0 = bias0[col], b1 = bias0[col + 1];
            sm[AS2_OFF + r0 * AS2_LD + col]     = to_tf32(fmaxf(acc[mt][nt][0] + b0, 0.f));
            sm[AS2_OFF + r0 * AS2_LD + col + 1] = to_tf32(fmaxf(acc[mt][nt][1] + b1, 0.f));
            sm[AS2_OFF + r1 * AS2_LD + col]     = to_tf32(fmaxf(acc[mt][nt][2] + b0, 0.f));
            sm[AS2_OFF + r1 * AS2_LD + col + 1] = to_tf32(fmaxf(acc[mt][nt][3] + b1, 0.f));
        }
    }
    __syncthreads();

    // ---- stage B: G_tile = Xt_tile @ Wc, K=256, A from smem ----
    #pragma unroll
    for (int mt = 0; mt < 2; mt++)
        #pragma unroll
        for (int nt = 0; nt < 8; nt++)
            #pragma unroll
            for (int i = 0; i < 4; i++) acc[mt][nt][i] = 0.f;

    auto load_b = [&](int st, int kc) {
        #pragma unroll
        for (int l = 0; l < 4; l++) {
            int idx = tid + l * 256;
            int k  = idx >> 6;
            int nc = (idx & 63) << 2;
            cp_async16(smb + (uint32_t)(BSB_OFF + st * BSB_SZ + k * 264 + nc) * 4u,
                       g_Wc + (size_t)(kc + k) * 256 + nc, 16);
        }
    };

    load_b(0, 0);
    CP_COMMIT();

    for (int it = 0; it < 16; it++) {
        if (it + 1 < 16) load_b((it + 1) & 1, (it + 1) * 16);
        CP_COMMIT();
        CP_WAIT1();
        __syncthreads();
        const float* bs = sm + BSB_OFF + (it & 1) * BSB_SZ;
        const float* a2 = sm + AS2_OFF;
        const int kg = it * 16;

        #pragma unroll
        for (int kk = 0; kk < 16; kk += 8) {
            uint32_t af[2][4], bf[8][2];
            #pragma unroll
            for (int mt = 0; mt < 2; mt++) {
                int mb = woffm + mt * 16;
                af[mt][0] = __float_as_uint(a2[(mb + g)     * AS2_LD + kg + kk + cq]);
                af[mt][1] = __float_as_uint(a2[(mb + g + 8) * AS2_LD + kg + kk + cq]);
                af[mt][2] = __float_as_uint(a2[(mb + g)     * AS2_LD + kg + kk + cq + 4]);
                af[mt][3] = __float_as_uint(a2[(mb + g + 8) * AS2_LD + kg + kk + cq + 4]);
            }
            #pragma unroll
            for (int nt = 0; nt < 8; nt++) {
                int n = woffn + nt * 8 + g;
                bf[nt][0] = __float_as_uint(bs[(kk + cq)     * 264 + n]);
                bf[nt][1] = __float_as_uint(bs[(kk + cq + 4) * 264 + n]);
            }
            #pragma unroll
            for (int mt = 0; mt < 2; mt++)
                #pragma unroll
                for (int nt = 0; nt < 8; nt++)
                    mma_tf32(acc[mt][nt], af[mt], bf[nt]);
        }
        __syncthreads();
    }

    // stage-B epilogue: raw gates to g_G (guarded)
    #pragma unroll
    for (int mt = 0; mt < 2; mt++) {
        int r0 = row0 + woffm + mt * 16 + g;
        int r1 = r0 + 8;
        #pragma unroll
        for (int nt = 0; nt < 8; nt++) {
            int col = woffn + nt * 8 + 2 * cq;
            if (r0 < M)
                *(float2*)(g_G + (size_t)r0 * 256 + col) = make_float2(acc[mt][nt][0], acc[mt][nt][1]);
            if (r1 < M)
                *(float2*)(g_G + (size_t)r1 * 256 + col) = make_float2(acc[mt][nt][2], acc[mt][nt][3]);
        }
    }
}

// ---------------- fused aggregate + bias + GRU + output head (warp-per-node) ----------------
// Each warp owns one node's full 256 features (2 float4 per lane). csr entries are
// prefetched into lanes and broadcast via shfl -> independent 1KB row gathers, 4x unroll.
__global__ __launch_bounds__(256) void k_agg_gru(const float* __restrict__ fcw,
                                                 const float* __restrict__ fcb,
                                                 float* __restrict__ hout,
                                                 float* __restrict__ out) {
    const int wid  = threadIdx.x >> 5;
    const int lane = threadIdx.x & 31;
    const int n    = blockIdx.x * 8 + wid;
    if (n >= Nn) return;

    const float4* G4 = (const float4*)g_G;     // row stride 64 float4
    const size_t rb = (size_t)n * 64;

    float4 a0 = make_float4(0.f, 0.f, 0.f, 0.f);
    float4 a1 = make_float4(0.f, 0.f, 0.f, 0.f);

    const int beg = g_rowptr[n];
    const int count = g_count[n];
    const int nf = count < 32 ? count : 32;

    int2 my = make_int2(0, 0);
    if (lane < nf) my = g_csr[beg + lane];

    int e = 0;
    for (; e + 4 <= nf; e += 4) {
        int s0 = __shfl_sync(0xffffffffu, my.x, e);
        int s1 = __shfl_sync(0xffffffffu, my.x, e + 1);
        int s2 = __shfl_sync(0xffffffffu, my.x, e + 2);
        int s3 = __shfl_sync(0xffffffffu, my.x, e + 3);
        float c0 = __int_as_float(__shfl_sync(0xffffffffu, my.y, e));
        float c1 = __int_as_float(__shfl_sync(0xffffffffu, my.y, e + 1));
        float c2 = __int_as_float(__shfl_sync(0xffffffffu, my.y, e + 2));
        float c3 = __int_as_float(__shfl_sync(0xffffffffu, my.y, e + 3));
        float4 u0 = G4[(size_t)s0 * 64 + lane], v0 = G4[(size_t)s0 * 64 + 32 + lane];
        float4 u1 = G4[(size_t)s1 * 64 + lane], v1 = G4[(size_t)s1 * 64 + 32 + lane];
        float4 u2 = G4[(size_t)s2 * 64 + lane], v2 = G4[(size_t)s2 * 64 + 32 + lane];
        float4 u3 = G4[(size_t)s3 * 64 + lane], v3 = G4[(size_t)s3 * 64 + 32 + lane];
        a0.x += c0*u0.x + c1*u1.x + c2*u2.x + c3*u3.x;
        a0.y += c0*u0.y + c1*u1.y + c2*u2.y + c3*u3.y;
        a0.z += c0*u0.z + c1*u1.z + c2*u2.z + c3*u3.z;
        a0.w += c0*u0.w + c1*u1.w + c2*u2.w + c3*u3.w;
        a1.x += c0*v0.x + c1*v1.x + c2*v2.x + c3*v3.x;
        a1.y += c0*v0.y + c1*v1.y + c2*v2.y + c3*v3.y;
        a1.z += c0*v0.z + c1*v1.z + c2*v2.z + c3*v3.z;
        a1.w += c0*v0.w + c1*v1.w + c2*v2.w + c3*v3.w;
    }
    for (; e < nf; e++) {
        int   s = __shfl_sync(0xffffffffu, my.x, e);
        float c = __int_as_float(__shfl_sync(0xffffffffu, my.y, e));
        float4 u = G4[(size_t)s * 64 + lane], v = G4[(size_t)s * 64 + 32 + lane];
        a0.x += c*u.x; a0.y += c*u.y; a0.z += c*u.z; a0.w += c*u.w;
        a1.x += c*v.x; a1.y += c*v.y; a1.z += c*v.z; a1.w += c*v.w;
    }
    for (int ee = 32; ee < count; ee++) {       // virtually never taken (Poisson(8))
        int2 p = g_csr[beg + ee];
        float c = __int_as_float(p.y);
        float4 u = G4[(size_t)p.x * 64 + lane], v = G4[(size_t)p.x * 64 + 32 + lane];
        a0.x += c*u.x; a0.y += c*u.y; a0.z += c*u.z; a0.w += c*u.w;
        a1.x += c*v.x; a1.y += c*v.y; a1.z += c*v.z; a1.w += c*v.w;
    }

    const float di  = g_dinv[n];
    const float di2 = di * di;
    float4 self0 = G4[rb + lane], self1 = G4[rb + 32 + lane];
    float4 bc0 = ((const float4*)g_bc)[lane];
    float4 bc1 = ((const float4*)g_bc)[32 + lane];

    float gz0 = a0.x * di + di2 * self0.x + bc0.x;
    float gh0 = a0.y * di + di2 * self0.y + bc0.y;
    float gz1 = a0.z * di + di2 * self0.z + bc0.z;
    float gh1 = a0.w * di + di2 * self0.w + bc0.w;
    float gz2 = a1.x * di + di2 * self1.x + bc1.x;
    float gh2 = a1.y * di + di2 * self1.y + bc1.y;
    float gz3 = a1.z * di + di2 * self1.z + bc1.z;
    float gh3 = a1.w * di + di2 * self1.w + bc1.w;

    float h0 = (1.f - 1.f / (1.f + expf(-gz0))) * tanhf(gh0);
    float h1 = (1.f - 1.f / (1.f + expf(-gz1))) * tanhf(gh1);
    float h2 = (1.f - 1.f / (1.f + expf(-gz2))) * tanhf(gh2);
    float h3 = (1.f - 1.f / (1.f + expf(-gz3))) * tanhf(gh3);

    *(float2*)(hout + (size_t)n * 128 + 2 * lane)      = make_float2(h0, h1);
    *(float2*)(hout + (size_t)n * 128 + 64 + 2 * lane) = make_float2(h2, h3);

    float2 w0 = ((const float2*)fcw)[lane];
    float2 w1 = ((const float2*)fcw)[32 + lane];
    float prod = fmaxf(h0, 0.f) * w0.x + fmaxf(h1, 0.f) * w0.y
               + fmaxf(h2, 0.f) * w1.x + fmaxf(h3, 0.f) * w1.y;
    #pragma unroll
    for (int o = 16; o; o >>= 1) prod += __shfl_xor_sync(0xffffffffu, prod, o);
    if (lane == 0) out[n] = prod + fcb[0];
}

// ---------------- launch ----------------
extern "C" void kernel_launch(void* const* d_in, const int* in_sizes, int n_in,
                              void* d_out, int out_size) {
    const float* x     = (const float*)d_in[0];
    const int*   ei    = (const int*)d_in[1];
    const float* ew    = (const float*)d_in[2];
    const float* fc0_w = (const float*)d_in[3];
    const float* fc0_b = (const float*)d_in[4];
    // d_in[5] = att: softmax over one element == 1.0
    const float* czw   = (const float*)d_in[6];
    const float* czb   = (const float*)d_in[7];
    const float* lzw   = (const float*)d_in[8];
    const float* lzb   = (const float*)d_in[9];
    // d_in[10..13] dead (H0 == 0 kills the R branch)
    const float* chw   = (const float*)d_in[14];
    const float* chb   = (const float*)d_in[15];
    const float* lhw   = (const float*)d_in[16];
    const float* lhb   = (const float*)d_in[17];
    const float* fcw   = (const float*)d_in[18];
    const float* fcb   = (const float*)d_in[19];

    const int* src = ei;
    const int* dst = ei + Ee;

    float* out  = (float*)d_out;
    float* hout = out + Nn;

    const int nb = (Nn + 1023) / 1024;
    const int gM = (Nn + 63) / 64;
    const int smem_bytes = SMEM_FLOATS * 4;

    static bool attr_done = false;
    if (!attr_done) {
        cudaFuncSetAttribute(k_gemm_fused, cudaFuncAttributeMaxDynamicSharedMemorySize, smem_bytes);
        attr_done = true;
    }

    // launch index 3 = fused GEMM (ncu capture slot)
    k_round_b0<<<(FIN * H1 + 255) / 256, 256>>>(fc0_w);
    k_build_wc<<<256, 128>>>(czw, chw, lzw, lhw);
    k_build_bc<<<1, 128>>>(czb, chb, lzw, lhw, lzb, lhb);

    k_gemm_fused<<<gM, 256, smem_bytes>>>(x, fc0_b, Nn);    // index 3

    k_init<<<(Nn + 255) / 256, 256>>>();
    k_edge_accum<<<(Ee + 255) / 256, 256>>>(dst, ew);
    k_dinv<<<(Nn + 255) / 256, 256>>>();
    k_scan_block<<<nb, 1024>>>();
    k_scan_sums<<<1, 32>>>(nb);
    k_scan_add<<<nb, 1024>>>();
    k_fill<<<(Ee + 255) / 256, 256>>>(src, dst, ew);

    k_agg_gru<<<(Nn + 7) / 8, 256>>>(fcw, fcb, hout, out);
}